// round 2
// baseline (speedup 1.0000x reference)
#include <cuda_runtime.h>
#include <math.h>

#define MAXN 50000
#define MAXE 400000
#define MAXET (MAXN + MAXE)
#define CDIV(a,b) (((a)+(b)-1)/(b))

// ---------------- scratch (static device arrays; no allocs allowed) ----------
__device__ float g_h1[MAXN*256];   // x@W1
__device__ float g_o1[MAXN*256];   // GAT1 out
__device__ float g_h2[MAXN*128];   // o1@W2
__device__ float g_o2[MAXN*128];   // GAT2 out
__device__ float g_g3[MAXN*64];    // o2@W3
__device__ float g_o3[MAXN*64];    // GCN1 out
__device__ float g_g4[MAXN*32];    // o3@W4
__device__ float g_es[MAXN*4];
__device__ float g_ed[MAXN*4];
__device__ float g_m [MAXN*4];
__device__ float g_s [MAXN*4];
__device__ float g_ex[MAXET*4];
__device__ float g_deg[MAXN];
__device__ float g_dinv[MAXN];
__device__ int   g_src[MAXET];
__device__ int   g_dst[MAXET];
__device__ float g_gsum[32];
__device__ int   g_is64;

// ---------------- helpers ----------------------------------------------------
__device__ __forceinline__ float atomicMaxFloat(float* addr, float value) {
    if (value >= 0.0f)
        return __int_as_float(atomicMax((int*)addr, __float_as_int(value)));
    else
        return __uint_as_float(atomicMin((unsigned int*)addr, __float_as_uint(value)));
}

__device__ __forceinline__ float elu1(float v) {
    return v > 0.0f ? v : expm1f(v);
}

// ---------------- dtype sniff + edge decode ----------------------------------
__global__ void sniff_kernel(const void* ei) {
    // If true dtype is int64 (little-endian, values < 2^31), every odd int32
    // word is 0. If int32, odd words are random node ids (P(all 0) ~ 0).
    const int* r = (const int*)ei;
    int is64 = 1;
    for (int k = 0; k < 128; k++)
        if (r[2*k + 1] != 0) { is64 = 0; break; }
    g_is64 = is64;
}

__global__ void decode_edges(const void* ei, int E, int n) {
    int e = blockIdx.x * blockDim.x + threadIdx.x;
    int Etot = E + n;
    if (e >= Etot) return;
    if (e < E) {
        if (g_is64) {
            const long long* p = (const long long*)ei;
            g_src[e] = (int)p[e];
            g_dst[e] = (int)p[(size_t)E + e];
        } else {
            const int* p = (const int*)ei;
            g_src[e] = p[e];
            g_dst[e] = p[E + e];
        }
    } else {
        g_src[e] = e - E;   // self loops
        g_dst[e] = e - E;
    }
}

// ---------------- generic fill ------------------------------------------------
__global__ void fill_kernel(float* p, float v, int count) {
    int i = blockIdx.x * blockDim.x + threadIdx.x;
    if (i < count) p[i] = v;
}

// ---------------- SGEMM: C[M,N] = A[M,K] @ B[K,N] ----------------------------
__global__ void sgemm(const float* __restrict__ A, const float* __restrict__ B,
                      float* __restrict__ C, int M, int N, int K)
{
    __shared__ float As[16][64];
    __shared__ float Bs[16][64];
    int tid = threadIdx.y * 16 + threadIdx.x;
    int rowBase = blockIdx.x * 64;
    int colBase = blockIdx.y * 64;
    float acc[4][4] = {};
    for (int k0 = 0; k0 < K; k0 += 16) {
        #pragma unroll
        for (int i = 0; i < 4; i++) {
            int idx = tid * 4 + i;          // 0..1023
            int m  = idx >> 4;
            int kk = idx & 15;
            int gr = rowBase + m, gc = k0 + kk;
            As[kk][m] = (gr < M && gc < K) ? A[(size_t)gr * K + gc] : 0.0f;
        }
        #pragma unroll
        for (int i = 0; i < 4; i++) {
            int idx = tid * 4 + i;
            int kk = idx >> 6;
            int nn = idx & 63;
            int gr = k0 + kk, gc = colBase + nn;
            Bs[kk][nn] = (gr < K && gc < N) ? B[(size_t)gr * N + gc] : 0.0f;
        }
        __syncthreads();
        #pragma unroll
        for (int kk = 0; kk < 16; kk++) {
            float a[4], b[4];
            #pragma unroll
            for (int i = 0; i < 4; i++) a[i] = As[kk][threadIdx.y * 4 + i];
            #pragma unroll
            for (int j = 0; j < 4; j++) b[j] = Bs[kk][threadIdx.x * 4 + j];
            #pragma unroll
            for (int i = 0; i < 4; i++)
                #pragma unroll
                for (int j = 0; j < 4; j++) acc[i][j] += a[i] * b[j];
        }
        __syncthreads();
    }
    #pragma unroll
    for (int i = 0; i < 4; i++) {
        int gr = rowBase + threadIdx.y * 4 + i;
        if (gr >= M) continue;
        #pragma unroll
        for (int j = 0; j < 4; j++) {
            int gc = colBase + threadIdx.x * 4 + j;
            if (gc < N) C[(size_t)gr * N + gc] = acc[i][j];
        }
    }
}

// ---------------- GAT attention ----------------------------------------------
__global__ void att_scores(const float* __restrict__ h,
                           const float* __restrict__ a_src,
                           const float* __restrict__ a_dst,
                           float* es, float* ed, int n, int H, int C)
{
    int idx = blockIdx.x * blockDim.x + threadIdx.x;
    if (idx >= n * H) return;
    int i = idx / H, hh = idx - i * H;
    const float* row = h + (size_t)i * H * C + hh * C;
    const float* as = a_src + hh * C;
    const float* ad = a_dst + hh * C;
    float s1 = 0.0f, s2 = 0.0f;
    for (int c = 0; c < C; c++) {
        float v = row[c];
        s1 += v * as[c];
        s2 += v * ad[c];
    }
    es[idx] = s1;
    ed[idx] = s2;
}

__global__ void att_pass1(const float* __restrict__ es, const float* __restrict__ ed,
                          float* m, int Etot, int H)
{
    int idx = blockIdx.x * blockDim.x + threadIdx.x;
    if (idx >= Etot * H) return;
    int e = idx / H, hh = idx - e * H;
    int s = g_src[e], d = g_dst[e];
    float v = es[s * H + hh] + ed[d * H + hh];
    v = v >= 0.0f ? v : 0.2f * v;
    atomicMaxFloat(&m[d * H + hh], v);
}

__global__ void att_pass2(const float* __restrict__ es, const float* __restrict__ ed,
                          const float* __restrict__ m, float* exbuf, float* ssum,
                          int Etot, int H)
{
    int idx = blockIdx.x * blockDim.x + threadIdx.x;
    if (idx >= Etot * H) return;
    int e = idx / H, hh = idx - e * H;
    int s = g_src[e], d = g_dst[e];
    float v = es[s * H + hh] + ed[d * H + hh];
    v = v >= 0.0f ? v : 0.2f * v;
    float ex = expf(v - m[d * H + hh]);
    exbuf[idx] = ex;
    atomicAdd(&ssum[d * H + hh], ex);
}

__global__ void att_pass3(const float* __restrict__ exbuf, const float* __restrict__ ssum,
                          const float* __restrict__ h, float* out,
                          int Etot, int H, int C)
{
    int idx = blockIdx.x * blockDim.x + threadIdx.x;
    int HC = H * C;
    if (idx >= Etot * HC) return;
    int e = idx / HC;
    int ch = idx - e * HC;
    int hh = ch / C;
    int s = g_src[e], d = g_dst[e];
    float alpha = exbuf[e * H + hh] / (ssum[d * H + hh] + 1e-16f);
    atomicAdd(&out[(size_t)d * HC + ch], h[(size_t)s * HC + ch] * alpha);
}

// ---------------- bias + ELU --------------------------------------------------
__global__ void bias_elu(float* io, const float* __restrict__ b, int n, int F)
{
    int idx = blockIdx.x * blockDim.x + threadIdx.x;
    if (idx >= n * F) return;
    int ch = idx % F;
    io[idx] = elu1(io[idx] + b[ch]);
}

// ---------------- GCN ---------------------------------------------------------
__global__ void count_deg(float* deg, int Etot)
{
    int e = blockIdx.x * blockDim.x + threadIdx.x;
    if (e >= Etot) return;
    atomicAdd(&deg[g_dst[e]], 1.0f);
}

__global__ void make_dinv(const float* __restrict__ deg, float* dinv, int n)
{
    int i = blockIdx.x * blockDim.x + threadIdx.x;
    if (i >= n) return;
    dinv[i] = rsqrtf(fmaxf(deg[i], 1e-12f));
}

__global__ void gcn_agg(const float* __restrict__ dinv, const float* __restrict__ h,
                        float* out, int Etot, int F)
{
    int idx = blockIdx.x * blockDim.x + threadIdx.x;
    if (idx >= Etot * F) return;
    int e = idx / F;
    int ch = idx - e * F;
    int s = g_src[e], d = g_dst[e];
    atomicAdd(&out[(size_t)d * F + ch], h[(size_t)s * F + ch] * dinv[s] * dinv[d]);
}

// ---------------- heads -------------------------------------------------------
__global__ void zone_head(const float* __restrict__ h, const float* __restrict__ Wz,
                          const float* __restrict__ bz, float* out, int n)
{
    int idx = blockIdx.x * blockDim.x + threadIdx.x;
    if (idx >= n * 4) return;
    int i = idx >> 2, j = idx & 3;
    float acc = bz[j];
    const float* row = h + (size_t)i * 32;
    #pragma unroll
    for (int k = 0; k < 32; k++) acc += row[k] * Wz[k * 4 + j];
    out[idx] = acc;
}

__global__ void mean_reduce(const float* __restrict__ h, float* gsum, int n)
{
    __shared__ float sm[256];
    int ch = threadIdx.x & 31;
    int grp = threadIdx.x >> 5;
    float acc = 0.0f;
    for (int r = blockIdx.x * 8 + grp; r < n; r += gridDim.x * 8)
        acc += h[(size_t)r * 32 + ch];
    sm[threadIdx.x] = acc;
    __syncthreads();
    if (grp == 0) {
        float t = 0.0f;
        #pragma unroll
        for (int g = 0; g < 8; g++) t += sm[g * 32 + ch];
        atomicAdd(&gsum[ch], t);
    }
}

__global__ void heads_kernel(const float* __restrict__ gsum,
                             const float* Ws, const float* bs,
                             const float* Wa, const float* ba,
                             const float* Wc, const float* bc,
                             float* out3, int n)
{
    int t = threadIdx.x;   // 32 threads
    float mean = gsum[t] / (float)n;
    float vs = mean * Ws[t];
    float va = mean * Wa[t];
    float vc = mean * Wc[t];
    #pragma unroll
    for (int o = 16; o > 0; o >>= 1) {
        vs += __shfl_down_sync(0xffffffffu, vs, o);
        va += __shfl_down_sync(0xffffffffu, va, o);
        vc += __shfl_down_sync(0xffffffffu, vc, o);
    }
    if (t == 0) {
        out3[0] = 1.0f / (1.0f + expf(-(vs + bs[0])));
        out3[1] = 1.0f / (1.0f + expf(-(va + ba[0])));
        out3[2] = 1.0f / (1.0f + expf(-(vc + bc[0])));
    }
}

// ---------------- launch ------------------------------------------------------
extern "C" void kernel_launch(void* const* d_in, const int* in_sizes, int n_in,
                              void* d_out, int out_size)
{
    const float* x      = (const float*)d_in[0];
    const void*  ei     = d_in[1];
    const float* W1     = (const float*)d_in[2];
    const float* a1_src = (const float*)d_in[3];
    const float* a1_dst = (const float*)d_in[4];
    const float* b1     = (const float*)d_in[5];
    const float* W2     = (const float*)d_in[6];
    const float* a2_src = (const float*)d_in[7];
    const float* a2_dst = (const float*)d_in[8];
    const float* b2     = (const float*)d_in[9];
    const float* W3     = (const float*)d_in[10];
    const float* b3     = (const float*)d_in[11];
    const float* W4     = (const float*)d_in[12];
    const float* b4     = (const float*)d_in[13];
    const float* Wz     = (const float*)d_in[14];
    const float* bz     = (const float*)d_in[15];
    const float* Ws     = (const float*)d_in[16];
    const float* bs     = (const float*)d_in[17];
    const float* Wa     = (const float*)d_in[18];
    const float* ba     = (const float*)d_in[19];
    const float* Wc     = (const float*)d_in[20];
    const float* bc     = (const float*)d_in[21];

    int n = in_sizes[0] / 10;
    int E = in_sizes[1] / 2;
    int Etot = E + n;

    float* out      = (float*)d_out;
    float* out_zone = out;
    float* out_sc   = out + (size_t)n * 4;
    float* out_h    = out + (size_t)n * 4 + 3;

    float *p_h1, *p_o1, *p_h2, *p_o2, *p_g3, *p_o3, *p_g4;
    float *p_es, *p_ed, *p_m, *p_s, *p_ex, *p_deg, *p_dinv, *p_gsum;
    cudaGetSymbolAddress((void**)&p_h1,  g_h1);
    cudaGetSymbolAddress((void**)&p_o1,  g_o1);
    cudaGetSymbolAddress((void**)&p_h2,  g_h2);
    cudaGetSymbolAddress((void**)&p_o2,  g_o2);
    cudaGetSymbolAddress((void**)&p_g3,  g_g3);
    cudaGetSymbolAddress((void**)&p_o3,  g_o3);
    cudaGetSymbolAddress((void**)&p_g4,  g_g4);
    cudaGetSymbolAddress((void**)&p_es,  g_es);
    cudaGetSymbolAddress((void**)&p_ed,  g_ed);
    cudaGetSymbolAddress((void**)&p_m,   g_m);
    cudaGetSymbolAddress((void**)&p_s,   g_s);
    cudaGetSymbolAddress((void**)&p_ex,  g_ex);
    cudaGetSymbolAddress((void**)&p_deg, g_deg);
    cudaGetSymbolAddress((void**)&p_dinv,g_dinv);
    cudaGetSymbolAddress((void**)&p_gsum,g_gsum);

    const int T = 256;
    const float NEG_BIG = -3.402823466e38f;
    dim3 tb(16, 16);

    // edge decode
    sniff_kernel<<<1, 1>>>(ei);
    decode_edges<<<CDIV(Etot, T), T>>>(ei, E, n);

    // ---- GAT1: 10 -> H=4, C=64 ----
    sgemm<<<dim3(CDIV(n, 64), CDIV(256, 64)), tb>>>(x, W1, p_h1, n, 256, 10);
    att_scores<<<CDIV(n * 4, T), T>>>(p_h1, a1_src, a1_dst, p_es, p_ed, n, 4, 64);
    fill_kernel<<<CDIV(n * 4, T), T>>>(p_m, NEG_BIG, n * 4);
    fill_kernel<<<CDIV(n * 4, T), T>>>(p_s, 0.0f, n * 4);
    fill_kernel<<<CDIV(n * 256, T), T>>>(p_o1, 0.0f, n * 256);
    att_pass1<<<CDIV(Etot * 4, T), T>>>(p_es, p_ed, p_m, Etot, 4);
    att_pass2<<<CDIV(Etot * 4, T), T>>>(p_es, p_ed, p_m, p_ex, p_s, Etot, 4);
    att_pass3<<<CDIV(Etot * 256, T), T>>>(p_ex, p_s, p_h1, p_o1, Etot, 4, 64);
    bias_elu<<<CDIV(n * 256, T), T>>>(p_o1, b1, n, 256);

    // ---- GAT2: 256 -> H=2, C=64 ----
    sgemm<<<dim3(CDIV(n, 64), CDIV(128, 64)), tb>>>(p_o1, W2, p_h2, n, 128, 256);
    att_scores<<<CDIV(n * 2, T), T>>>(p_h2, a2_src, a2_dst, p_es, p_ed, n, 2, 64);
    fill_kernel<<<CDIV(n * 2, T), T>>>(p_m, NEG_BIG, n * 2);
    fill_kernel<<<CDIV(n * 2, T), T>>>(p_s, 0.0f, n * 2);
    fill_kernel<<<CDIV(n * 128, T), T>>>(p_o2, 0.0f, n * 128);
    att_pass1<<<CDIV(Etot * 2, T), T>>>(p_es, p_ed, p_m, Etot, 2);
    att_pass2<<<CDIV(Etot * 2, T), T>>>(p_es, p_ed, p_m, p_ex, p_s, Etot, 2);
    att_pass3<<<CDIV(Etot * 128, T), T>>>(p_ex, p_s, p_h2, p_o2, Etot, 2, 64);
    bias_elu<<<CDIV(n * 128, T), T>>>(p_o2, b2, n, 128);

    // ---- degrees (shared by both GCN layers) ----
    fill_kernel<<<CDIV(n, T), T>>>(p_deg, 0.0f, n);
    count_deg<<<CDIV(Etot, T), T>>>(p_deg, Etot);
    make_dinv<<<CDIV(n, T), T>>>(p_deg, p_dinv, n);

    // ---- GCN1: 128 -> 64 ----
    sgemm<<<dim3(CDIV(n, 64), 1), tb>>>(p_o2, W3, p_g3, n, 64, 128);
    fill_kernel<<<CDIV(n * 64, T), T>>>(p_o3, 0.0f, n * 64);
    gcn_agg<<<CDIV(Etot * 64, T), T>>>(p_dinv, p_g3, p_o3, Etot, 64);
    bias_elu<<<CDIV(n * 64, T), T>>>(p_o3, b3, n, 64);

    // ---- GCN2: 64 -> 32 (aggregate directly into the output h region) ----
    sgemm<<<dim3(CDIV(n, 64), 1), tb>>>(p_o3, W4, p_g4, n, 32, 64);
    fill_kernel<<<CDIV(n * 32, T), T>>>(out_h, 0.0f, n * 32);
    gcn_agg<<<CDIV(Etot * 32, T), T>>>(p_dinv, p_g4, out_h, Etot, 32);
    bias_elu<<<CDIV(n * 32, T), T>>>(out_h, b4, n, 32);

    // ---- heads ----
    zone_head<<<CDIV(n * 4, T), T>>>(out_h, Wz, bz, out_zone, n);
    fill_kernel<<<1, 32>>>(p_gsum, 0.0f, 32);
    mean_reduce<<<128, 256>>>(out_h, p_gsum, n);
    heads_kernel<<<1, 32>>>(p_gsum, Ws, bs, Wa, ba, Wc, bc, out_sc, n);
}

// round 5
// speedup vs baseline: 2.1661x; 2.1661x over previous
#include <cuda_runtime.h>
#include <math.h>

#define MAXN 50000
#define MAXE 400000
#define MAXET (MAXN + MAXE)
#define CDIV(a,b) (((a)+(b)-1)/(b))
#define MAXDEG 512

// ---------------- scratch (static device arrays; no allocs allowed) ----------
__device__ float g_h1[MAXN*256];
__device__ float g_o1[MAXN*256];
__device__ float g_h2[MAXN*128];
__device__ float g_o2[MAXN*128];
__device__ float g_g3[MAXN*64];
__device__ float g_o3[MAXN*64];
__device__ float g_g4[MAXN*32];
__device__ float g_es[MAXN*4];
__device__ float g_ed[MAXN*4];
__device__ int   g_src[MAXET];
__device__ int   g_dst[MAXET];
__device__ int   g_degi[MAXN];
__device__ int   g_rp[MAXN+1];
__device__ int   g_woff[MAXN];
__device__ int   g_csr[MAXET];
__device__ float g_dinv[MAXN];
__device__ float g_gsum[32];
__device__ int   g_is64;

// ---------------- dtype sniff + edge decode ----------------------------------
__global__ void sniff_kernel(const void* ei) {
    const int* r = (const int*)ei;
    int is64 = 1;
    for (int k = 0; k < 128; k++)
        if (r[2*k + 1] != 0) { is64 = 0; break; }
    g_is64 = is64;
}

__global__ void decode_edges(const void* ei, int E, int n) {
    int e = blockIdx.x * blockDim.x + threadIdx.x;
    int Etot = E + n;
    if (e >= Etot) return;
    int s, d;
    if (e < E) {
        if (g_is64) {
            const long long* p = (const long long*)ei;
            s = (int)p[e];
            d = (int)p[(size_t)E + e];
        } else {
            const int* p = (const int*)ei;
            s = p[e];
            d = p[E + e];
        }
    } else {
        s = e - E;
        d = e - E;
    }
    // defensive clamp: a mis-sniffed dtype must never produce OOB indices
    s = s < 0 ? 0 : (s >= n ? n - 1 : s);
    d = d < 0 ? 0 : (d >= n ? n - 1 : d);
    g_src[e] = s;
    g_dst[e] = d;
}

// ---------------- CSR build ---------------------------------------------------
__global__ void zero_degi(int n) {
    int i = blockIdx.x * blockDim.x + threadIdx.x;
    if (i < n) g_degi[i] = 0;
    if (i <= n) g_rp[i] = 0;
}

__global__ void count_deg(int Etot) {
    int e = blockIdx.x * blockDim.x + threadIdx.x;
    if (e >= Etot) return;
    atomicAdd(&g_degi[g_dst[e]], 1);
}

__global__ void scan_kernel(int n) {
    __shared__ int sm[1024];
    __shared__ int carry;
    if (threadIdx.x == 0) { carry = 0; g_rp[0] = 0; }
    __syncthreads();
    for (int base = 0; base < n; base += 1024) {
        int i = base + threadIdx.x;
        int v = (i < n) ? g_degi[i] : 0;
        sm[threadIdx.x] = v;
        __syncthreads();
        for (int off = 1; off < 1024; off <<= 1) {
            int t = (threadIdx.x >= off) ? sm[threadIdx.x - off] : 0;
            __syncthreads();
            sm[threadIdx.x] += t;
            __syncthreads();
        }
        if (i < n) g_rp[i + 1] = carry + sm[threadIdx.x];
        __syncthreads();
        if (threadIdx.x == 0) carry += sm[1023];
        __syncthreads();
    }
}

__global__ void copy_woff(int n) {
    int i = blockIdx.x * blockDim.x + threadIdx.x;
    if (i < n) g_woff[i] = g_rp[i];
}

__global__ void scatter_csr(int Etot) {
    int e = blockIdx.x * blockDim.x + threadIdx.x;
    if (e >= Etot) return;
    int d = g_dst[e];
    int pos = atomicAdd(&g_woff[d], 1);
    if (pos >= 0 && pos < MAXET) g_csr[pos] = g_src[e];
}

__global__ void make_dinv(int n) {
    int i = blockIdx.x * blockDim.x + threadIdx.x;
    if (i >= n) return;
    g_dinv[i] = rsqrtf(fmaxf((float)g_degi[i], 1e-12f));
}

// ---------------- small-K GEMM (layer 1, K=10) --------------------------------
__global__ void gemm_smallk(const float* __restrict__ A, const float* __restrict__ W,
                            float* __restrict__ C, int M, int N, int K)
{
    __shared__ float xs[8][16];
    int c = threadIdx.x;
    int row0 = blockIdx.x * 8;
    float w[16];
    for (int k = 0; k < K; k++) w[k] = W[k * N + c];
    for (int t = threadIdx.x; t < 8 * K; t += N) {
        int r = t / K, k = t - r * K;
        int gr = row0 + r;
        xs[r][k] = (gr < M) ? A[(size_t)gr * K + k] : 0.0f;
    }
    __syncthreads();
    for (int r = 0; r < 8; r++) {
        int gr = row0 + r;
        if (gr >= M) break;
        float acc = 0.0f;
        for (int k = 0; k < K; k++) acc += xs[r][k] * w[k];
        C[(size_t)gr * N + c] = acc;
    }
}

// ---------------- SGEMM: C[M,N] = A[M,K] @ B[K,N] ----------------------------
__global__ void sgemm(const float* __restrict__ A, const float* __restrict__ B,
                      float* __restrict__ C, int M, int N, int K)
{
    __shared__ float As[16][64];
    __shared__ float Bs[16][64];
    int tid = threadIdx.y * 16 + threadIdx.x;
    int rowBase = blockIdx.x * 64;
    int colBase = blockIdx.y * 64;
    float acc[4][4] = {};
    for (int k0 = 0; k0 < K; k0 += 16) {
        #pragma unroll
        for (int i = 0; i < 4; i++) {
            int idx = tid * 4 + i;
            int m  = idx >> 4;
            int kk = idx & 15;
            int gr = rowBase + m, gc = k0 + kk;
            As[kk][m] = (gr < M && gc < K) ? A[(size_t)gr * K + gc] : 0.0f;
        }
        #pragma unroll
        for (int i = 0; i < 4; i++) {
            int idx = tid * 4 + i;
            int kk = idx >> 6;
            int nn = idx & 63;
            int gr = k0 + kk, gc = colBase + nn;
            Bs[kk][nn] = (gr < K && gc < N) ? B[(size_t)gr * N + gc] : 0.0f;
        }
        __syncthreads();
        #pragma unroll
        for (int kk = 0; kk < 16; kk++) {
            float a[4], b[4];
            #pragma unroll
            for (int i = 0; i < 4; i++) a[i] = As[kk][threadIdx.y * 4 + i];
            #pragma unroll
            for (int j = 0; j < 4; j++) b[j] = Bs[kk][threadIdx.x * 4 + j];
            #pragma unroll
            for (int i = 0; i < 4; i++)
                #pragma unroll
                for (int j = 0; j < 4; j++) acc[i][j] += a[i] * b[j];
        }
        __syncthreads();
    }
    #pragma unroll
    for (int i = 0; i < 4; i++) {
        int gr = rowBase + threadIdx.y * 4 + i;
        if (gr >= M) continue;
        #pragma unroll
        for (int j = 0; j < 4; j++) {
            int gc = colBase + threadIdx.x * 4 + j;
            if (gc < N) C[(size_t)gr * N + gc] = acc[i][j];
        }
    }
}

// ---------------- attention scores: warp per node -----------------------------
template<int H, int C>
__global__ void att_scores_w(const float* __restrict__ h,
                             const float* __restrict__ a_src,
                             const float* __restrict__ a_dst,
                             float* __restrict__ es, float* __restrict__ ed, int n)
{
    const int HC = H * C;
    int gtid = blockIdx.x * blockDim.x + threadIdx.x;
    int node = gtid >> 5;
    int lane = threadIdx.x & 31;
    if (node >= n) return;
    const float4* row = (const float4*)(h + (size_t)node * HC);
    const float4* as4 = (const float4*)a_src;
    const float4* ad4 = (const float4*)a_dst;
    float accs[H], accd[H];
    #pragma unroll
    for (int hh = 0; hh < H; hh++) { accs[hh] = 0.0f; accd[hh] = 0.0f; }
    #pragma unroll
    for (int it = 0; it < HC / 128; it++) {
        int i4 = it * 32 + lane;
        float4 v = row[i4];
        int hh = i4 >> 4;
        float4 a = as4[hh * 16 + (i4 & 15)];
        float4 b = ad4[hh * 16 + (i4 & 15)];
        accs[hh] += v.x*a.x + v.y*a.y + v.z*a.z + v.w*a.w;
        accd[hh] += v.x*b.x + v.y*b.y + v.z*b.z + v.w*b.w;
    }
    #pragma unroll
    for (int hh = 0; hh < H; hh++) {
        #pragma unroll
        for (int off = 16; off; off >>= 1) {
            accs[hh] += __shfl_xor_sync(0xffffffffu, accs[hh], off);
            accd[hh] += __shfl_xor_sync(0xffffffffu, accd[hh], off);
        }
    }
    if (lane == 0) {
        #pragma unroll
        for (int hh = 0; hh < H; hh++) {
            es[node * H + hh] = accs[hh];
            ed[node * H + hh] = accd[hh];
        }
    }
}

// ---------------- fused GAT aggregation (per dst node, CSR) -------------------
template<int H, int C>
__global__ void gat_fused(const float* __restrict__ h,
                          const float* __restrict__ es, const float* __restrict__ ed,
                          const float* __restrict__ b,
                          float* __restrict__ out, int n)
{
    const int HC = H * C;          // == blockDim.x
    __shared__ int   srcs[MAXDEG];
    __shared__ float ebuf[MAXDEG * H];
    __shared__ float sh[H];

    int d   = blockIdx.x;
    int tid = threadIdx.x;
    int r0  = g_rp[d];
    int deg = g_rp[d + 1] - r0;
    if (r0 < 0) r0 = 0;
    if (deg < 0) deg = 0;
    if (deg > MAXDEG) deg = MAXDEG;
    if (r0 + deg > MAXET) deg = MAXET - r0 > 0 ? MAXET - r0 : 0;

    float edv[H];
    #pragma unroll
    for (int hh = 0; hh < H; hh++) edv[hh] = ed[d * H + hh];

    // phase 0: gather src ids + leaky-relu scores into smem
    for (int j = tid; j < deg; j += HC) {
        int s = g_csr[r0 + j];
        srcs[j] = s;
        #pragma unroll
        for (int hh = 0; hh < H; hh++) {
            float v = es[s * H + hh] + edv[hh];
            v = v >= 0.0f ? v : 0.2f * v;
            ebuf[j * H + hh] = v;
        }
    }
    __syncthreads();

    // phase 1+2: warp hh computes max, exponentiates in place, computes sum
    int warp = tid >> 5, lane = tid & 31;
    if (warp < H) {
        int hh = warp;
        float m = -3.402823466e38f;
        for (int j = lane; j < deg; j += 32) m = fmaxf(m, ebuf[j * H + hh]);
        #pragma unroll
        for (int off = 16; off; off >>= 1)
            m = fmaxf(m, __shfl_xor_sync(0xffffffffu, m, off));
        float s = 0.0f;
        for (int j = lane; j < deg; j += 32) {
            float ex = __expf(ebuf[j * H + hh] - m);
            ebuf[j * H + hh] = ex;
            s += ex;
        }
        #pragma unroll
        for (int off = 16; off; off >>= 1)
            s += __shfl_xor_sync(0xffffffffu, s, off);
        if (lane == 0) sh[hh] = s;
    }
    __syncthreads();

    // phase 3: weighted aggregate over edges
    int c = tid;
    int hc = c / C;
    float acc = 0.0f;
    int j = 0;
    for (; j + 4 <= deg; j += 4) {
        float e0 = ebuf[(j + 0) * H + hc];
        float e1 = ebuf[(j + 1) * H + hc];
        float e2 = ebuf[(j + 2) * H + hc];
        float e3 = ebuf[(j + 3) * H + hc];
        float h0 = h[(size_t)srcs[j + 0] * HC + c];
        float h1 = h[(size_t)srcs[j + 1] * HC + c];
        float h2 = h[(size_t)srcs[j + 2] * HC + c];
        float h3 = h[(size_t)srcs[j + 3] * HC + c];
        acc += e0 * h0 + e1 * h1 + e2 * h2 + e3 * h3;
    }
    for (; j < deg; j++)
        acc += ebuf[j * H + hc] * h[(size_t)srcs[j] * HC + c];

    float o = acc / (sh[hc] + 1e-16f) + b[c];
    out[(size_t)d * HC + c] = o > 0.0f ? o : expm1f(o);
}

// ---------------- fused GCN aggregation (per dst node, CSR) -------------------
template<int F>
__global__ void gcn_fused(const float* __restrict__ h,
                          const float* __restrict__ dinv,
                          const float* __restrict__ b,
                          float* __restrict__ out, int n)
{
    const int G = 128 / F;
    int g = threadIdx.x / F, c = threadIdx.x % F;
    int d = blockIdx.x * G + g;
    if (d >= n) return;
    int r0 = g_rp[d], deg = g_rp[d + 1] - r0;
    if (r0 < 0) r0 = 0;
    if (deg < 0) deg = 0;
    if (deg > MAXDEG) deg = MAXDEG;
    if (r0 + deg > MAXET) deg = MAXET - r0 > 0 ? MAXET - r0 : 0;
    float acc = 0.0f;
    int j = 0;
    for (; j + 4 <= deg; j += 4) {
        int s0 = g_csr[r0 + j + 0];
        int s1 = g_csr[r0 + j + 1];
        int s2 = g_csr[r0 + j + 2];
        int s3 = g_csr[r0 + j + 3];
        acc += dinv[s0] * h[(size_t)s0 * F + c]
             + dinv[s1] * h[(size_t)s1 * F + c]
             + dinv[s2] * h[(size_t)s2 * F + c]
             + dinv[s3] * h[(size_t)s3 * F + c];
    }
    for (; j < deg; j++) {
        int s = g_csr[r0 + j];
        acc += dinv[s] * h[(size_t)s * F + c];
    }
    float o = dinv[d] * acc + b[c];
    out[(size_t)d * F + c] = o > 0.0f ? o : expm1f(o);
}

// ---------------- heads -------------------------------------------------------
__global__ void zone_head(const float* __restrict__ h, const float* __restrict__ Wz,
                          const float* __restrict__ bz, float* out, int n)
{
    int idx = blockIdx.x * blockDim.x + threadIdx.x;
    if (idx >= n * 4) return;
    int i = idx >> 2, j = idx & 3;
    float acc = bz[j];
    const float* row = h + (size_t)i * 32;
    #pragma unroll
    for (int k = 0; k < 32; k++) acc += row[k] * Wz[k * 4 + j];
    out[idx] = acc;
}

__global__ void zero_gsum() {
    if (threadIdx.x < 32) g_gsum[threadIdx.x] = 0.0f;
}

__global__ void mean_reduce(const float* __restrict__ h, int n)
{
    __shared__ float sm[256];
    int ch = threadIdx.x & 31;
    int grp = threadIdx.x >> 5;
    float acc = 0.0f;
    for (int r = blockIdx.x * 8 + grp; r < n; r += gridDim.x * 8)
        acc += h[(size_t)r * 32 + ch];
    sm[threadIdx.x] = acc;
    __syncthreads();
    if (grp == 0) {
        float t = 0.0f;
        #pragma unroll
        for (int g = 0; g < 8; g++) t += sm[g * 32 + ch];
        atomicAdd(&g_gsum[ch], t);
    }
}

__global__ void heads_kernel(const float* Ws, const float* bs,
                             const float* Wa, const float* ba,
                             const float* Wc, const float* bc,
                             float* out3, int n)
{
    int t = threadIdx.x;
    float mean = g_gsum[t] / (float)n;
    float vs = mean * Ws[t];
    float va = mean * Wa[t];
    float vc = mean * Wc[t];
    #pragma unroll
    for (int o = 16; o > 0; o >>= 1) {
        vs += __shfl_down_sync(0xffffffffu, vs, o);
        va += __shfl_down_sync(0xffffffffu, va, o);
        vc += __shfl_down_sync(0xffffffffu, vc, o);
    }
    if (t == 0) {
        out3[0] = 1.0f / (1.0f + expf(-(vs + bs[0])));
        out3[1] = 1.0f / (1.0f + expf(-(va + ba[0])));
        out3[2] = 1.0f / (1.0f + expf(-(vc + bc[0])));
    }
}

// ---------------- launch ------------------------------------------------------
extern "C" void kernel_launch(void* const* d_in, const int* in_sizes, int n_in,
                              void* d_out, int out_size)
{
    const float* x      = (const float*)d_in[0];
    const void*  ei     = d_in[1];
    const float* W1     = (const float*)d_in[2];
    const float* a1_src = (const float*)d_in[3];
    const float* a1_dst = (const float*)d_in[4];
    const float* b1     = (const float*)d_in[5];
    const float* W2     = (const float*)d_in[6];
    const float* a2_src = (const float*)d_in[7];
    const float* a2_dst = (const float*)d_in[8];
    const float* b2     = (const float*)d_in[9];
    const float* W3     = (const float*)d_in[10];
    const float* b3     = (const float*)d_in[11];
    const float* W4     = (const float*)d_in[12];
    const float* b4     = (const float*)d_in[13];
    const float* Wz     = (const float*)d_in[14];
    const float* bz     = (const float*)d_in[15];
    const float* Ws     = (const float*)d_in[16];
    const float* bs     = (const float*)d_in[17];
    const float* Wa     = (const float*)d_in[18];
    const float* ba     = (const float*)d_in[19];
    const float* Wc     = (const float*)d_in[20];
    const float* bc     = (const float*)d_in[21];

    int n = in_sizes[0] / 10;
    int E = in_sizes[1] / 2;
    int Etot = E + n;

    float* out      = (float*)d_out;
    float* out_zone = out;
    float* out_sc   = out + (size_t)n * 4;
    float* out_h    = out + (size_t)n * 4 + 3;

    float *p_h1, *p_o1, *p_h2, *p_o2, *p_g3, *p_o3, *p_g4, *p_es, *p_ed, *p_dinv;
    cudaGetSymbolAddress((void**)&p_h1,  g_h1);
    cudaGetSymbolAddress((void**)&p_o1,  g_o1);
    cudaGetSymbolAddress((void**)&p_h2,  g_h2);
    cudaGetSymbolAddress((void**)&p_o2,  g_o2);
    cudaGetSymbolAddress((void**)&p_g3,  g_g3);
    cudaGetSymbolAddress((void**)&p_o3,  g_o3);
    cudaGetSymbolAddress((void**)&p_g4,  g_g4);
    cudaGetSymbolAddress((void**)&p_es,  g_es);
    cudaGetSymbolAddress((void**)&p_ed,  g_ed);
    cudaGetSymbolAddress((void**)&p_dinv,g_dinv);

    const int T = 256;
    dim3 tb(16, 16);

    // ---- edge decode + CSR build ----
    sniff_kernel<<<1, 1>>>(ei);
    decode_edges<<<CDIV(Etot, T), T>>>(ei, E, n);
    zero_degi<<<CDIV(n + 1, T), T>>>(n);
    count_deg<<<CDIV(Etot, T), T>>>(Etot);
    scan_kernel<<<1, 1024>>>(n);
    copy_woff<<<CDIV(n, T), T>>>(n);
    scatter_csr<<<CDIV(Etot, T), T>>>(Etot);
    make_dinv<<<CDIV(n, T), T>>>(n);

    // ---- GAT1: 10 -> H=4, C=64 ----
    gemm_smallk<<<CDIV(n, 8), 256>>>(x, W1, p_h1, n, 256, 10);
    att_scores_w<4, 64><<<CDIV(n * 32, T), T>>>(p_h1, a1_src, a1_dst, p_es, p_ed, n);
    gat_fused<4, 64><<<n, 256>>>(p_h1, p_es, p_ed, b1, p_o1, n);

    // ---- GAT2: 256 -> H=2, C=64 ----
    sgemm<<<dim3(CDIV(n, 64), 2), tb>>>(p_o1, W2, p_h2, n, 128, 256);
    att_scores_w<2, 64><<<CDIV(n * 32, T), T>>>(p_h2, a2_src, a2_dst, p_es, p_ed, n);
    gat_fused<2, 64><<<n, 128>>>(p_h2, p_es, p_ed, b2, p_o2, n);

    // ---- GCN1: 128 -> 64 ----
    sgemm<<<dim3(CDIV(n, 64), 1), tb>>>(p_o2, W3, p_g3, n, 64, 128);
    gcn_fused<64><<<CDIV(n, 2), 128>>>(p_g3, p_dinv, b3, p_o3, n);

    // ---- GCN2: 64 -> 32 (writes straight into output h region) ----
    sgemm<<<dim3(CDIV(n, 64), 1), tb>>>(p_o3, W4, p_g4, n, 32, 64);
    gcn_fused<32><<<CDIV(n, 4), 128>>>(p_g4, p_dinv, b4, out_h, n);

    // ---- heads ----
    zone_head<<<CDIV(n * 4, T), T>>>(out_h, Wz, bz, out_zone, n);
    zero_gsum<<<1, 32>>>();
    mean_reduce<<<128, 256>>>(out_h, n);
    heads_kernel<<<1, 32>>>(Ws, bs, Wa, ba, Wc, bc, out_sc, n);
}

// round 7
// speedup vs baseline: 2.8337x; 1.3082x over previous
#include <cuda_runtime.h>
#include <math.h>

#define MAXN 50000
#define MAXE 400000
#define MAXET (MAXN + MAXE)
#define CDIV(a,b) (((a)+(b)-1)/(b))
#define MAXDEG 512

// ---------------- scratch ----------------------------------------------------
__device__ float g_xagg[MAXN*40];   // GAT1: per-node per-head aggregated x (4*10)
__device__ float g_o1[MAXN*256];
__device__ float g_h2[MAXN*128];
__device__ float g_o2[MAXN*128];
__device__ float g_g3[MAXN*64];
__device__ float g_o3[MAXN*64];
__device__ float g_g4[MAXN*32];
__device__ float g_es[MAXN*4];
__device__ float g_ed[MAXN*4];
__device__ int   g_src[MAXET];
__device__ int   g_dst[MAXET];
__device__ int   g_degi[MAXN];
__device__ int   g_rp[MAXN+1];
__device__ int   g_woff[MAXN];
__device__ int   g_csr[MAXET];
__device__ float g_dinv[MAXN];
__device__ float g_gsum[32];
__device__ float g_ws1[40];         // (W1 @ a1_src) : [k=10][h=4]
__device__ float g_wd1[40];
__device__ int   g_is64;

// ---------------- dtype sniff + fused edge decode + degree count --------------
__global__ void sniff_kernel(const void* ei) {
    const int* r = (const int*)ei;
    int is64 = 1;
    for (int k = 0; k < 128; k++)
        if (r[2*k + 1] != 0) { is64 = 0; break; }
    g_is64 = is64;
}

__global__ void zero_degi(int n) {
    int i = blockIdx.x * blockDim.x + threadIdx.x;
    if (i < n) g_degi[i] = 0;
    if (i <= n) g_rp[i] = 0;
}

__global__ void decode_count(const void* ei, int E, int n) {
    int e = blockIdx.x * blockDim.x + threadIdx.x;
    int Etot = E + n;
    if (e >= Etot) return;
    int s, d;
    if (e < E) {
        if (g_is64) {
            const long long* p = (const long long*)ei;
            s = (int)p[e];
            d = (int)p[(size_t)E + e];
        } else {
            const int* p = (const int*)ei;
            s = p[e];
            d = p[E + e];
        }
    } else {
        s = e - E;
        d = e - E;
    }
    s = s < 0 ? 0 : (s >= n ? n - 1 : s);
    d = d < 0 ? 0 : (d >= n ? n - 1 : d);
    g_src[e] = s;
    g_dst[e] = d;
    atomicAdd(&g_degi[d], 1);
}

// ---------------- single-block warp-shuffle scan (writes rp + woff) -----------
__global__ void scan_kernel(int n) {
    const int T = 1024;
    __shared__ int warpsum[32];
    int tid = threadIdx.x;
    int per = (n + T - 1) / T;
    int start = tid * per;
    int end = start + per; if (end > n) end = n;
    int sum = 0;
    for (int i = start; i < end; i++) sum += g_degi[i];
    int lane = tid & 31, wid = tid >> 5;
    int v = sum;
    #pragma unroll
    for (int off = 1; off < 32; off <<= 1) {
        int t = __shfl_up_sync(0xffffffffu, v, off);
        if (lane >= off) v += t;
    }
    if (lane == 31) warpsum[wid] = v;
    __syncthreads();
    if (wid == 0) {
        int w = warpsum[lane];
        #pragma unroll
        for (int off = 1; off < 32; off <<= 1) {
            int t = __shfl_up_sync(0xffffffffu, w, off);
            if (lane >= off) w += t;
        }
        warpsum[lane] = w;
    }
    __syncthreads();
    int excl = v - sum + (wid > 0 ? warpsum[wid - 1] : 0);
    int run = excl;
    for (int i = start; i < end; i++) {
        g_rp[i] = run;
        g_woff[i] = run;
        run += g_degi[i];
    }
    if (end == n && end > start) g_rp[n] = run;
}

__global__ void scatter_csr(int Etot) {
    int e = blockIdx.x * blockDim.x + threadIdx.x;
    if (e >= Etot) return;
    int d = g_dst[e];
    int pos = atomicAdd(&g_woff[d], 1);
    if (pos >= 0 && pos < MAXET) g_csr[pos] = g_src[e];
}

__global__ void make_dinv(int n) {
    int i = blockIdx.x * blockDim.x + threadIdx.x;
    if (i >= n) return;
    g_dinv[i] = rsqrtf(fmaxf((float)g_degi[i], 1e-12f));
}

// ---------------- GAT1: projected attention vectors ---------------------------
// ws[k][h] = sum_c W1[k, h*64+c] * a1_src[h][c]   (and same for dst)
__global__ void proj_att1(const float* __restrict__ W1,
                          const float* __restrict__ a1s,
                          const float* __restrict__ a1d) {
    int t = threadIdx.x;  // 80 threads
    if (t >= 80) return;
    int which = t / 40;
    int r = t % 40;
    int k = r / 4, h = r % 4;
    const float* a = which ? a1d : a1s;
    float s = 0.0f;
    for (int c = 0; c < 64; c++) s += W1[k * 256 + h * 64 + c] * a[h * 64 + c];
    if (which) g_wd1[k * 4 + h] = s; else g_ws1[k * 4 + h] = s;
}

// es[i][h] = x[i] . ws[:,h]  (h1 never materialized)
__global__ void att1_scores(const float* __restrict__ x, int n) {
    int i = blockIdx.x * blockDim.x + threadIdx.x;
    if (i >= n) return;
    float xr[10];
    #pragma unroll
    for (int k = 0; k < 10; k++) xr[k] = x[(size_t)i * 10 + k];
    #pragma unroll
    for (int h = 0; h < 4; h++) {
        float s1 = 0.0f, s2 = 0.0f;
        #pragma unroll
        for (int k = 0; k < 10; k++) {
            s1 += xr[k] * g_ws1[k * 4 + h];
            s2 += xr[k] * g_wd1[k * 4 + h];
        }
        g_es[i * 4 + h] = s1;
        g_ed[i * 4 + h] = s2;
    }
}

// one thread per dst node: softmax over edges (2-pass), aggregate x (10 ch x 4 heads)
__global__ void gat1_agg(const float* __restrict__ x, int n) {
    int d = blockIdx.x * blockDim.x + threadIdx.x;
    if (d >= n) return;
    int r0 = g_rp[d];
    int deg = g_rp[d + 1] - r0;
    if (r0 < 0) r0 = 0;
    if (deg < 0) deg = 0;
    if (r0 + deg > MAXET) deg = MAXET - r0 > 0 ? MAXET - r0 : 0;

    float edv[4];
    #pragma unroll
    for (int h = 0; h < 4; h++) edv[h] = g_ed[d * 4 + h];

    // pass 1: per-head max
    float m[4];
    #pragma unroll
    for (int h = 0; h < 4; h++) m[h] = -3.402823466e38f;
    for (int j = 0; j < deg; j++) {
        int s = g_csr[r0 + j];
        #pragma unroll
        for (int h = 0; h < 4; h++) {
            float v = g_es[s * 4 + h] + edv[h];
            v = v >= 0.0f ? v : 0.2f * v;
            m[h] = fmaxf(m[h], v);
        }
    }
    // pass 2: exp-sum + aggregate x
    float ssum[4] = {0.f, 0.f, 0.f, 0.f};
    float acc[4][10];
    #pragma unroll
    for (int h = 0; h < 4; h++)
        #pragma unroll
        for (int k = 0; k < 10; k++) acc[h][k] = 0.0f;
    for (int j = 0; j < deg; j++) {
        int s = g_csr[r0 + j];
        float xr[10];
        #pragma unroll
        for (int k = 0; k < 10; k++) xr[k] = x[(size_t)s * 10 + k];
        #pragma unroll
        for (int h = 0; h < 4; h++) {
            float v = g_es[s * 4 + h] + edv[h];
            v = v >= 0.0f ? v : 0.2f * v;
            float ex = __expf(v - m[h]);
            ssum[h] += ex;
            #pragma unroll
            for (int k = 0; k < 10; k++) acc[h][k] += ex * xr[k];
        }
    }
    #pragma unroll
    for (int h = 0; h < 4; h++) {
        float inv = 1.0f / (ssum[h] + 1e-16f);
        #pragma unroll
        for (int k = 0; k < 10; k++)
            g_xagg[(size_t)d * 40 + h * 10 + k] = acc[h][k] * inv;
    }
}

// o1[d, h*64+c] = elu( xagg[d,h,:] . W1[:, h*64+c] + b1 )
__global__ void gat1_out(const float* __restrict__ W1, const float* __restrict__ b1,
                         float* __restrict__ out, int n) {
    __shared__ float xs[8][40];
    int c = threadIdx.x;               // 256
    int row0 = blockIdx.x * 8;
    int h = c >> 6;
    float w[10];
    #pragma unroll
    for (int k = 0; k < 10; k++) w[k] = W1[k * 256 + c];
    for (int t = threadIdx.x; t < 8 * 40; t += 256) {
        int r = t / 40, k = t - r * 40;
        int gr = row0 + r;
        xs[r][k] = (gr < n) ? g_xagg[(size_t)gr * 40 + k] : 0.0f;
    }
    __syncthreads();
    float bc = b1[c];
    for (int r = 0; r < 8; r++) {
        int gr = row0 + r;
        if (gr >= n) break;
        float acc = 0.0f;
        #pragma unroll
        for (int k = 0; k < 10; k++) acc += xs[r][h * 10 + k] * w[k];
        float o = acc + bc;
        out[(size_t)gr * 256 + c] = o > 0.0f ? o : expm1f(o);
    }
}

// ---------------- SGEMM 128x128 tile, 8x8 microtile (for GEMM2) ---------------
__global__ void sgemm128(const float* __restrict__ A, const float* __restrict__ B,
                         float* __restrict__ C, int M, int N, int K)
{
    __shared__ float As[16][128];
    __shared__ float Bs[16][128];
    int tid = threadIdx.x;            // 256
    int tx = tid & 15, ty = tid >> 4;
    int rowBase = blockIdx.x * 128;
    int colBase = blockIdx.y * 128;
    float acc[8][8] = {};
    for (int k0 = 0; k0 < K; k0 += 16) {
        #pragma unroll
        for (int q = 0; q < 2; q++) {
            int idx = tid * 2 + q;            // 0..511
            int m = idx >> 2, kq = (idx & 3) * 4;
            int gr = rowBase + m;
            float4 v = make_float4(0.f, 0.f, 0.f, 0.f);
            if (gr < M) v = *(const float4*)(A + (size_t)gr * K + k0 + kq);
            As[kq + 0][m] = v.x;
            As[kq + 1][m] = v.y;
            As[kq + 2][m] = v.z;
            As[kq + 3][m] = v.w;
        }
        #pragma unroll
        for (int q = 0; q < 2; q++) {
            int idx = tid * 2 + q;
            int kk = idx >> 5, n4 = (idx & 31) * 4;
            int gc = colBase + n4;
            float4 v = make_float4(0.f, 0.f, 0.f, 0.f);
            if (gc + 3 < N) v = *(const float4*)(B + (size_t)(k0 + kk) * N + gc);
            *(float4*)&Bs[kk][n4] = v;
        }
        __syncthreads();
        #pragma unroll
        for (int kk = 0; kk < 16; kk++) {
            float a[8], b[8];
            #pragma unroll
            for (int i = 0; i < 8; i++) a[i] = As[kk][ty * 8 + i];
            #pragma unroll
            for (int j = 0; j < 8; j++) b[j] = Bs[kk][tx * 8 + j];
            #pragma unroll
            for (int i = 0; i < 8; i++)
                #pragma unroll
                for (int j = 0; j < 8; j++) acc[i][j] += a[i] * b[j];
        }
        __syncthreads();
    }
    #pragma unroll
    for (int i = 0; i < 8; i++) {
        int gr = rowBase + ty * 8 + i;
        if (gr >= M) continue;
        #pragma unroll
        for (int j = 0; j < 8; j++) {
            int gc = colBase + tx * 8 + j;
            if (gc < N) C[(size_t)gr * N + gc] = acc[i][j];
        }
    }
}

// ---------------- generic 64-tile SGEMM (GEMM3/GEMM4) -------------------------
__global__ void sgemm(const float* __restrict__ A, const float* __restrict__ B,
                      float* __restrict__ C, int M, int N, int K)
{
    __shared__ float As[16][64];
    __shared__ float Bs[16][64];
    int tid = threadIdx.y * 16 + threadIdx.x;
    int rowBase = blockIdx.x * 64;
    int colBase = blockIdx.y * 64;
    float acc[4][4] = {};
    for (int k0 = 0; k0 < K; k0 += 16) {
        #pragma unroll
        for (int i = 0; i < 4; i++) {
            int idx = tid * 4 + i;
            int m  = idx >> 4;
            int kk = idx & 15;
            int gr = rowBase + m, gc = k0 + kk;
            As[kk][m] = (gr < M && gc < K) ? A[(size_t)gr * K + gc] : 0.0f;
        }
        #pragma unroll
        for (int i = 0; i < 4; i++) {
            int idx = tid * 4 + i;
            int kk = idx >> 6;
            int nn = idx & 63;
            int gr = k0 + kk, gc = colBase + nn;
            Bs[kk][nn] = (gr < K && gc < N) ? B[(size_t)gr * N + gc] : 0.0f;
        }
        __syncthreads();
        #pragma unroll
        for (int kk = 0; kk < 16; kk++) {
            float a[4], b[4];
            #pragma unroll
            for (int i = 0; i < 4; i++) a[i] = As[kk][threadIdx.y * 4 + i];
            #pragma unroll
            for (int j = 0; j < 4; j++) b[j] = Bs[kk][threadIdx.x * 4 + j];
            #pragma unroll
            for (int i = 0; i < 4; i++)
                #pragma unroll
                for (int j = 0; j < 4; j++) acc[i][j] += a[i] * b[j];
        }
        __syncthreads();
    }
    #pragma unroll
    for (int i = 0; i < 4; i++) {
        int gr = rowBase + threadIdx.y * 4 + i;
        if (gr >= M) continue;
        #pragma unroll
        for (int j = 0; j < 4; j++) {
            int gc = colBase + threadIdx.x * 4 + j;
            if (gc < N) C[(size_t)gr * N + gc] = acc[i][j];
        }
    }
}

// ---------------- attention scores (GAT2): warp per node ----------------------
template<int H, int C>
__global__ void att_scores_w(const float* __restrict__ h,
                             const float* __restrict__ a_src,
                             const float* __restrict__ a_dst,
                             float* __restrict__ es, float* __restrict__ ed, int n)
{
    const int HC = H * C;
    int gtid = blockIdx.x * blockDim.x + threadIdx.x;
    int node = gtid >> 5;
    int lane = threadIdx.x & 31;
    if (node >= n) return;
    const float4* row = (const float4*)(h + (size_t)node * HC);
    const float4* as4 = (const float4*)a_src;
    const float4* ad4 = (const float4*)a_dst;
    float accs[H], accd[H];
    #pragma unroll
    for (int hh = 0; hh < H; hh++) { accs[hh] = 0.0f; accd[hh] = 0.0f; }
    #pragma unroll
    for (int it = 0; it < HC / 128; it++) {
        int i4 = it * 32 + lane;
        float4 v = row[i4];
        int hh = i4 >> 4;
        float4 a = as4[hh * 16 + (i4 & 15)];
        float4 b = ad4[hh * 16 + (i4 & 15)];
        accs[hh] += v.x*a.x + v.y*a.y + v.z*a.z + v.w*a.w;
        accd[hh] += v.x*b.x + v.y*b.y + v.z*b.z + v.w*b.w;
    }
    #pragma unroll
    for (int hh = 0; hh < H; hh++) {
        #pragma unroll
        for (int off = 16; off; off >>= 1) {
            accs[hh] += __shfl_xor_sync(0xffffffffu, accs[hh], off);
            accd[hh] += __shfl_xor_sync(0xffffffffu, accd[hh], off);
        }
    }
    if (lane == 0) {
        #pragma unroll
        for (int hh = 0; hh < H; hh++) {
            es[node * H + hh] = accs[hh];
            ed[node * H + hh] = accd[hh];
        }
    }
}

// ---------------- fused GAT aggregation (block per dst node) ------------------
template<int H, int C>
__global__ void gat_fused(const float* __restrict__ h,
                          const float* __restrict__ es, const float* __restrict__ ed,
                          const float* __restrict__ b,
                          float* __restrict__ out, int n)
{
    const int HC = H * C;
    __shared__ int   srcs[MAXDEG];
    __shared__ float ebuf[MAXDEG * H];
    __shared__ float sh[H];

    int d   = blockIdx.x;
    int tid = threadIdx.x;
    int r0  = g_rp[d];
    int deg = g_rp[d + 1] - r0;
    if (r0 < 0) r0 = 0;
    if (deg < 0) deg = 0;
    if (deg > MAXDEG) deg = MAXDEG;
    if (r0 + deg > MAXET) deg = MAXET - r0 > 0 ? MAXET - r0 : 0;

    float edv[H];
    #pragma unroll
    for (int hh = 0; hh < H; hh++) edv[hh] = ed[d * H + hh];

    for (int j = tid; j < deg; j += HC) {
        int s = g_csr[r0 + j];
        srcs[j] = s;
        #pragma unroll
        for (int hh = 0; hh < H; hh++) {
            float v = es[s * H + hh] + edv[hh];
            v = v >= 0.0f ? v : 0.2f * v;
            ebuf[j * H + hh] = v;
        }
    }
    __syncthreads();

    int warp = tid >> 5, lane = tid & 31;
    if (warp < H) {
        int hh = warp;
        float m = -3.402823466e38f;
        for (int j = lane; j < deg; j += 32) m = fmaxf(m, ebuf[j * H + hh]);
        #pragma unroll
        for (int off = 16; off; off >>= 1)
            m = fmaxf(m, __shfl_xor_sync(0xffffffffu, m, off));
        float s = 0.0f;
        for (int j = lane; j < deg; j += 32) {
            float ex = __expf(ebuf[j * H + hh] - m);
            ebuf[j * H + hh] = ex;
            s += ex;
        }
        #pragma unroll
        for (int off = 16; off; off >>= 1)
            s += __shfl_xor_sync(0xffffffffu, s, off);
        if (lane == 0) sh[hh] = s;
    }
    __syncthreads();

    int c = tid;
    int hc = c / C;
    float acc = 0.0f;
    int j = 0;
    for (; j + 4 <= deg; j += 4) {
        float e0 = ebuf[(j + 0) * H + hc];
        float e1 = ebuf[(j + 1) * H + hc];
        float e2 = ebuf[(j + 2) * H + hc];
        float e3 = ebuf[(j + 3) * H + hc];
        float h0 = h[(size_t)srcs[j + 0] * HC + c];
        float h1 = h[(size_t)srcs[j + 1] * HC + c];
        float h2 = h[(size_t)srcs[j + 2] * HC + c];
        float h3 = h[(size_t)srcs[j + 3] * HC + c];
        acc += e0 * h0 + e1 * h1 + e2 * h2 + e3 * h3;
    }
    for (; j < deg; j++)
        acc += ebuf[j * H + hc] * h[(size_t)srcs[j] * HC + c];

    float o = acc / (sh[hc] + 1e-16f) + b[c];
    out[(size_t)d * HC + c] = o > 0.0f ? o : expm1f(o);
}

// ---------------- fused GCN aggregation ---------------------------------------
template<int F>
__global__ void gcn_fused(const float* __restrict__ h,
                          const float* __restrict__ dinv,
                          const float* __restrict__ b,
                          float* __restrict__ out, int n)
{
    const int G = 128 / F;
    int g = threadIdx.x / F, c = threadIdx.x % F;
    int d = blockIdx.x * G + g;
    if (d >= n) return;
    int r0 = g_rp[d], deg = g_rp[d + 1] - r0;
    if (r0 < 0) r0 = 0;
    if (deg < 0) deg = 0;
    if (r0 + deg > MAXET) deg = MAXET - r0 > 0 ? MAXET - r0 : 0;
    float acc = 0.0f;
    int j = 0;
    for (; j + 4 <= deg; j += 4) {
        int s0 = g_csr[r0 + j + 0];
        int s1 = g_csr[r0 + j + 1];
        int s2 = g_csr[r0 + j + 2];
        int s3 = g_csr[r0 + j + 3];
        acc += dinv[s0] * h[(size_t)s0 * F + c]
             + dinv[s1] * h[(size_t)s1 * F + c]
             + dinv[s2] * h[(size_t)s2 * F + c]
             + dinv[s3] * h[(size_t)s3 * F + c];
    }
    for (; j < deg; j++) {
        int s = g_csr[r0 + j];
        acc += dinv[s] * h[(size_t)s * F + c];
    }
    float o = dinv[d] * acc + b[c];
    out[(size_t)d * F + c] = o > 0.0f ? o : expm1f(o);
}

// ---------------- heads -------------------------------------------------------
__global__ void zone_head(const float* __restrict__ h, const float* __restrict__ Wz,
                          const float* __restrict__ bz, float* out, int n)
{
    int idx = blockIdx.x * blockDim.x + threadIdx.x;
    if (idx >= n * 4) return;
    int i = idx >> 2, j = idx & 3;
    float acc = bz[j];
    const float* row = h + (size_t)i * 32;
    #pragma unroll
    for (int k = 0; k < 32; k++) acc += row[k] * Wz[k * 4 + j];
    out[idx] = acc;
}

__global__ void zero_gsum() {
    if (threadIdx.x < 32) g_gsum[threadIdx.x] = 0.0f;
}

__global__ void mean_reduce(const float* __restrict__ h, int n)
{
    __shared__ float sm[256];
    int ch = threadIdx.x & 31;
    int grp = threadIdx.x >> 5;
    float acc = 0.0f;
    for (int r = blockIdx.x * 8 + grp; r < n; r += gridDim.x * 8)
        acc += h[(size_t)r * 32 + ch];
    sm[threadIdx.x] = acc;
    __syncthreads();
    if (grp == 0) {
        float t = 0.0f;
        #pragma unroll
        for (int g = 0; g < 8; g++) t += sm[g * 32 + ch];
        atomicAdd(&g_gsum[ch], t);
    }
}

__global__ void heads_kernel(const float* Ws, const float* bs,
                             const float* Wa, const float* ba,
                             const float* Wc, const float* bc,
                             float* out3, int n)
{
    int t = threadIdx.x;
    float mean = g_gsum[t] / (float)n;
    float vs = mean * Ws[t];
    float va = mean * Wa[t];
    float vc = mean * Wc[t];
    #pragma unroll
    for (int o = 16; o > 0; o >>= 1) {
        vs += __shfl_down_sync(0xffffffffu, vs, o);
        va += __shfl_down_sync(0xffffffffu, va, o);
        vc += __shfl_down_sync(0xffffffffu, vc, o);
    }
    if (t == 0) {
        out3[0] = 1.0f / (1.0f + expf(-(vs + bs[0])));
        out3[1] = 1.0f / (1.0f + expf(-(va + ba[0])));
        out3[2] = 1.0f / (1.0f + expf(-(vc + bc[0])));
    }
}

// ---------------- launch ------------------------------------------------------
extern "C" void kernel_launch(void* const* d_in, const int* in_sizes, int n_in,
                              void* d_out, int out_size)
{
    const float* x      = (const float*)d_in[0];
    const void*  ei     = d_in[1];
    const float* W1     = (const float*)d_in[2];
    const float* a1_src = (const float*)d_in[3];
    const float* a1_dst = (const float*)d_in[4];
    const float* b1     = (const float*)d_in[5];
    const float* W2     = (const float*)d_in[6];
    const float* a2_src = (const float*)d_in[7];
    const float* a2_dst = (const float*)d_in[8];
    const float* b2     = (const float*)d_in[9];
    const float* W3     = (const float*)d_in[10];
    const float* b3     = (const float*)d_in[11];
    const float* W4     = (const float*)d_in[12];
    const float* b4     = (const float*)d_in[13];
    const float* Wz     = (const float*)d_in[14];
    const float* bz     = (const float*)d_in[15];
    const float* Ws     = (const float*)d_in[16];
    const float* bs     = (const float*)d_in[17];
    const float* Wa     = (const float*)d_in[18];
    const float* ba     = (const float*)d_in[19];
    const float* Wc     = (const float*)d_in[20];
    const float* bc     = (const float*)d_in[21];

    int n = in_sizes[0] / 10;
    int E = in_sizes[1] / 2;
    int Etot = E + n;

    float* out      = (float*)d_out;
    float* out_zone = out;
    float* out_sc   = out + (size_t)n * 4;
    float* out_h    = out + (size_t)n * 4 + 3;

    float *p_o1, *p_h2, *p_o2, *p_g3, *p_o3, *p_g4, *p_es, *p_ed, *p_dinv;
    cudaGetSymbolAddress((void**)&p_o1,  g_o1);
    cudaGetSymbolAddress((void**)&p_h2,  g_h2);
    cudaGetSymbolAddress((void**)&p_o2,  g_o2);
    cudaGetSymbolAddress((void**)&p_g3,  g_g3);
    cudaGetSymbolAddress((void**)&p_o3,  g_o3);
    cudaGetSymbolAddress((void**)&p_g4,  g_g4);
    cudaGetSymbolAddress((void**)&p_es,  g_es);
    cudaGetSymbolAddress((void**)&p_ed,  g_ed);
    cudaGetSymbolAddress((void**)&p_dinv,g_dinv);

    const int T = 256;
    dim3 tb(16, 16);

    // ---- CSR build ----
    sniff_kernel<<<1, 1>>>(ei);
    zero_degi<<<CDIV(n + 1, T), T>>>(n);
    decode_count<<<CDIV(Etot, T), T>>>(ei, E, n);
    scan_kernel<<<1, 1024>>>(n);
    scatter_csr<<<CDIV(Etot, T), T>>>(Etot);
    make_dinv<<<CDIV(n, T), T>>>(n);

    // ---- GAT1: aggregate x (10 ch), then project (h1 never materialized) ----
    proj_att1<<<1, 128>>>(W1, a1_src, a1_dst);
    att1_scores<<<CDIV(n, T), T>>>(x, n);
    gat1_agg<<<CDIV(n, 128), 128>>>(x, n);
    gat1_out<<<CDIV(n, 8), 256>>>(W1, b1, p_o1, n);

    // ---- GAT2: 256 -> H=2, C=64 ----
    sgemm128<<<dim3(CDIV(n, 128), 1), 256>>>(p_o1, W2, p_h2, n, 128, 256);
    att_scores_w<2, 64><<<CDIV(n * 32, T), T>>>(p_h2, a2_src, a2_dst, p_es, p_ed, n);
    gat_fused<2, 64><<<n, 128>>>(p_h2, p_es, p_ed, b2, p_o2, n);

    // ---- GCN1: 128 -> 64 ----
    sgemm<<<dim3(CDIV(n, 64), 1), tb>>>(p_o2, W3, p_g3, n, 64, 128);
    gcn_fused<64><<<CDIV(n, 2), 128>>>(p_g3, p_dinv, b3, p_o3, n);

    // ---- GCN2: 64 -> 32 ----
    sgemm<<<dim3(CDIV(n, 64), 1), tb>>>(p_o3, W4, p_g4, n, 32, 64);
    gcn_fused<32><<<CDIV(n, 4), 128>>>(p_g4, p_dinv, b4, out_h, n);

    // ---- heads ----
    zone_head<<<CDIV(n * 4, T), T>>>(out_h, Wz, bz, out_zone, n);
    zero_gsum<<<1, 32>>>();
    mean_reduce<<<128, 256>>>(out_h, n);
    heads_kernel<<<1, 32>>>(Ws, bs, Wa, ba, Wc, bc, out_sc, n);
}

// round 8
// speedup vs baseline: 3.3198x; 1.1715x over previous
#include <cuda_runtime.h>
#include <math.h>

#define MAXN 50000
#define MAXE 400000
#define MAXET (MAXN + MAXE)
#define CDIV(a,b) (((a)+(b)-1)/(b))
#define MAXDEG 512
#define SCAN_CHUNK 1024
#define MAXBLK 64    // CDIV(MAXN, SCAN_CHUNK) = 49

// ---------------- scratch ----------------------------------------------------
__device__ float g_xagg[MAXN*40];
__device__ float g_o1[MAXN*256];
__device__ float g_h2[MAXN*128];
__device__ float g_o2[MAXN*128];
__device__ float g_g3[MAXN*64];
__device__ float g_o3[MAXN*64];
__device__ float g_g4[MAXN*32];
__device__ float g_es[MAXN*4];
__device__ float g_ed[MAXN*4];
__device__ int   g_src[MAXET];
__device__ int   g_dst[MAXET];
__device__ int   g_degi[MAXN];
__device__ int   g_rp[MAXN+1];
__device__ int   g_woff[MAXN];
__device__ int   g_csr[MAXET];
__device__ float g_dinv[MAXN];
__device__ float g_gsum[32];
__device__ float g_ws1[40];
__device__ float g_wd1[40];
__device__ int   g_bsum[MAXBLK];
__device__ int   g_boff[MAXBLK];
__device__ int   g_is64;

// ---------------- dtype sniff + fused edge decode + degree count --------------
__global__ void sniff_kernel(const void* ei) {
    const int* r = (const int*)ei;
    int is64 = 1;
    for (int k = 0; k < 128; k++)
        if (r[2*k + 1] != 0) { is64 = 0; break; }
    g_is64 = is64;
}

__global__ void zero_degi(int n) {
    int i = blockIdx.x * blockDim.x + threadIdx.x;
    if (i < n) g_degi[i] = 0;
}

__global__ void decode_count(const void* ei, int E, int n) {
    int e = blockIdx.x * blockDim.x + threadIdx.x;
    int Etot = E + n;
    if (e >= Etot) return;
    int s, d;
    if (e < E) {
        if (g_is64) {
            const long long* p = (const long long*)ei;
            s = (int)p[e];
            d = (int)p[(size_t)E + e];
        } else {
            const int* p = (const int*)ei;
            s = p[e];
            d = p[E + e];
        }
    } else {
        s = e - E;
        d = e - E;
    }
    s = s < 0 ? 0 : (s >= n ? n - 1 : s);
    d = d < 0 ? 0 : (d >= n ? n - 1 : d);
    g_src[e] = s;
    g_dst[e] = d;
    atomicAdd(&g_degi[d], 1);
}

// ---------------- 3-phase multi-block exclusive scan ---------------------------
// phase A: per-block sums over SCAN_CHUNK degrees
__global__ void scan_a(int n) {
    __shared__ int wsum[8];
    int b = blockIdx.x;
    int base = b * SCAN_CHUNK;
    int tid = threadIdx.x;          // 256
    int s = 0;
    #pragma unroll
    for (int q = 0; q < 4; q++) {
        int i = base + tid * 4 + q;
        if (i < n) s += g_degi[i];
    }
    #pragma unroll
    for (int off = 16; off; off >>= 1) s += __shfl_xor_sync(0xffffffffu, s, off);
    if ((tid & 31) == 0) wsum[tid >> 5] = s;
    __syncthreads();
    if (tid == 0) {
        int t = 0;
        #pragma unroll
        for (int w = 0; w < 8; w++) t += wsum[w];
        g_bsum[b] = t;
    }
}

// phase B: single warp scans block sums; also writes rp[n] (= total)
__global__ void scan_b(int nb, int n) {
    int lane = threadIdx.x;         // 32
    int v0 = (2 * lane     < nb) ? g_bsum[2 * lane]     : 0;
    int v1 = (2 * lane + 1 < nb) ? g_bsum[2 * lane + 1] : 0;
    int s = v0 + v1;
    int inc = s;
    #pragma unroll
    for (int off = 1; off < 32; off <<= 1) {
        int t = __shfl_up_sync(0xffffffffu, inc, off);
        if (lane >= off) inc += t;
    }
    int excl = inc - s;
    if (2 * lane     < nb) g_boff[2 * lane]     = excl;
    if (2 * lane + 1 < nb) g_boff[2 * lane + 1] = excl + v0;
    if (lane == 31) g_rp[n] = inc;
}

// phase C: block-local exclusive scan + block offset; writes rp, woff, dinv
__global__ void scan_c(int n) {
    __shared__ int woffs[8];
    int b = blockIdx.x;
    int base = b * SCAN_CHUNK;
    int tid = threadIdx.x;          // 256
    int lane = tid & 31, w = tid >> 5;
    int d[4];
    int s = 0;
    #pragma unroll
    for (int q = 0; q < 4; q++) {
        int i = base + tid * 4 + q;
        d[q] = (i < n) ? g_degi[i] : 0;
        s += d[q];
    }
    int inc = s;
    #pragma unroll
    for (int off = 1; off < 32; off <<= 1) {
        int t = __shfl_up_sync(0xffffffffu, inc, off);
        if (lane >= off) inc += t;
    }
    if (lane == 31) woffs[w] = inc;
    __syncthreads();
    if (tid == 0) {
        int run = 0;
        #pragma unroll
        for (int i = 0; i < 8; i++) { int t = woffs[i]; woffs[i] = run; run += t; }
    }
    __syncthreads();
    int excl = inc - s + woffs[w] + g_boff[b];
    #pragma unroll
    for (int q = 0; q < 4; q++) {
        int i = base + tid * 4 + q;
        if (i < n) {
            g_rp[i] = excl;
            g_woff[i] = excl;
            excl += d[q];
            g_dinv[i] = rsqrtf(fmaxf((float)d[q], 1e-12f));
        }
    }
}

__global__ void scatter_csr(int Etot) {
    int e = blockIdx.x * blockDim.x + threadIdx.x;
    if (e >= Etot) return;
    int d = g_dst[e];
    int pos = atomicAdd(&g_woff[d], 1);
    if (pos >= 0 && pos < MAXET) g_csr[pos] = g_src[e];
}

// ---------------- GAT1: projected attention vectors ---------------------------
__global__ void proj_att1(const float* __restrict__ W1,
                          const float* __restrict__ a1s,
                          const float* __restrict__ a1d) {
    int t = threadIdx.x;
    if (t >= 80) return;
    int which = t / 40;
    int r = t % 40;
    int k = r / 4, h = r % 4;
    const float* a = which ? a1d : a1s;
    float s = 0.0f;
    for (int c = 0; c < 64; c++) s += W1[k * 256 + h * 64 + c] * a[h * 64 + c];
    if (which) g_wd1[k * 4 + h] = s; else g_ws1[k * 4 + h] = s;
}

__global__ void att1_scores(const float* __restrict__ x, int n) {
    int i = blockIdx.x * blockDim.x + threadIdx.x;
    if (i >= n) return;
    float xr[10];
    #pragma unroll
    for (int k = 0; k < 10; k++) xr[k] = x[(size_t)i * 10 + k];
    #pragma unroll
    for (int h = 0; h < 4; h++) {
        float s1 = 0.0f, s2 = 0.0f;
        #pragma unroll
        for (int k = 0; k < 10; k++) {
            s1 += xr[k] * g_ws1[k * 4 + h];
            s2 += xr[k] * g_wd1[k * 4 + h];
        }
        g_es[i * 4 + h] = s1;
        g_ed[i * 4 + h] = s2;
    }
}

__global__ void gat1_agg(const float* __restrict__ x, int n) {
    int d = blockIdx.x * blockDim.x + threadIdx.x;
    if (d >= n) return;
    int r0 = g_rp[d];
    int deg = g_rp[d + 1] - r0;
    if (r0 < 0) r0 = 0;
    if (deg < 0) deg = 0;
    if (r0 + deg > MAXET) deg = MAXET - r0 > 0 ? MAXET - r0 : 0;

    float edv[4];
    #pragma unroll
    for (int h = 0; h < 4; h++) edv[h] = g_ed[d * 4 + h];

    float m[4];
    #pragma unroll
    for (int h = 0; h < 4; h++) m[h] = -3.402823466e38f;
    for (int j = 0; j < deg; j++) {
        int s = g_csr[r0 + j];
        #pragma unroll
        for (int h = 0; h < 4; h++) {
            float v = g_es[s * 4 + h] + edv[h];
            v = v >= 0.0f ? v : 0.2f * v;
            m[h] = fmaxf(m[h], v);
        }
    }
    float ssum[4] = {0.f, 0.f, 0.f, 0.f};
    float acc[4][10];
    #pragma unroll
    for (int h = 0; h < 4; h++)
        #pragma unroll
        for (int k = 0; k < 10; k++) acc[h][k] = 0.0f;
    for (int j = 0; j < deg; j++) {
        int s = g_csr[r0 + j];
        float xr[10];
        #pragma unroll
        for (int k = 0; k < 10; k++) xr[k] = x[(size_t)s * 10 + k];
        #pragma unroll
        for (int h = 0; h < 4; h++) {
            float v = g_es[s * 4 + h] + edv[h];
            v = v >= 0.0f ? v : 0.2f * v;
            float ex = __expf(v - m[h]);
            ssum[h] += ex;
            #pragma unroll
            for (int k = 0; k < 10; k++) acc[h][k] += ex * xr[k];
        }
    }
    #pragma unroll
    for (int h = 0; h < 4; h++) {
        float inv = 1.0f / (ssum[h] + 1e-16f);
        #pragma unroll
        for (int k = 0; k < 10; k++)
            g_xagg[(size_t)d * 40 + h * 10 + k] = acc[h][k] * inv;
    }
}

__global__ void gat1_out(const float* __restrict__ W1, const float* __restrict__ b1,
                         float* __restrict__ out, int n) {
    __shared__ float xs[8][40];
    int c = threadIdx.x;
    int row0 = blockIdx.x * 8;
    int h = c >> 6;
    float w[10];
    #pragma unroll
    for (int k = 0; k < 10; k++) w[k] = W1[k * 256 + c];
    for (int t = threadIdx.x; t < 8 * 40; t += 256) {
        int r = t / 40, k = t - r * 40;
        int gr = row0 + r;
        xs[r][k] = (gr < n) ? g_xagg[(size_t)gr * 40 + k] : 0.0f;
    }
    __syncthreads();
    float bc = b1[c];
    for (int r = 0; r < 8; r++) {
        int gr = row0 + r;
        if (gr >= n) break;
        float acc = 0.0f;
        #pragma unroll
        for (int k = 0; k < 10; k++) acc += xs[r][h * 10 + k] * w[k];
        float o = acc + bc;
        out[(size_t)gr * 256 + c] = o > 0.0f ? o : expm1f(o);
    }
}

// ---------------- SGEMM 128x128 tile, 8x8 microtile ---------------------------
__global__ void sgemm128(const float* __restrict__ A, const float* __restrict__ B,
                         float* __restrict__ C, int M, int N, int K)
{
    __shared__ float As[16][128];
    __shared__ float Bs[16][128];
    int tid = threadIdx.x;
    int tx = tid & 15, ty = tid >> 4;
    int rowBase = blockIdx.x * 128;
    int colBase = blockIdx.y * 128;
    float acc[8][8] = {};
    for (int k0 = 0; k0 < K; k0 += 16) {
        #pragma unroll
        for (int q = 0; q < 2; q++) {
            int idx = tid * 2 + q;
            int m = idx >> 2, kq = (idx & 3) * 4;
            int gr = rowBase + m;
            float4 v = make_float4(0.f, 0.f, 0.f, 0.f);
            if (gr < M) v = *(const float4*)(A + (size_t)gr * K + k0 + kq);
            As[kq + 0][m] = v.x;
            As[kq + 1][m] = v.y;
            As[kq + 2][m] = v.z;
            As[kq + 3][m] = v.w;
        }
        #pragma unroll
        for (int q = 0; q < 2; q++) {
            int idx = tid * 2 + q;
            int kk = idx >> 5, n4 = (idx & 31) * 4;
            int gc = colBase + n4;
            float4 v = make_float4(0.f, 0.f, 0.f, 0.f);
            if (gc + 3 < N) v = *(const float4*)(B + (size_t)(k0 + kk) * N + gc);
            *(float4*)&Bs[kk][n4] = v;
        }
        __syncthreads();
        #pragma unroll
        for (int kk = 0; kk < 16; kk++) {
            float a[8], b[8];
            #pragma unroll
            for (int i = 0; i < 8; i++) a[i] = As[kk][ty * 8 + i];
            #pragma unroll
            for (int j = 0; j < 8; j++) b[j] = Bs[kk][tx * 8 + j];
            #pragma unroll
            for (int i = 0; i < 8; i++)
                #pragma unroll
                for (int j = 0; j < 8; j++) acc[i][j] += a[i] * b[j];
        }
        __syncthreads();
    }
    #pragma unroll
    for (int i = 0; i < 8; i++) {
        int gr = rowBase + ty * 8 + i;
        if (gr >= M) continue;
        #pragma unroll
        for (int j = 0; j < 8; j++) {
            int gc = colBase + tx * 8 + j;
            if (gc < N) C[(size_t)gr * N + gc] = acc[i][j];
        }
    }
}

// ---------------- generic 64-tile SGEMM ---------------------------------------
__global__ void sgemm(const float* __restrict__ A, const float* __restrict__ B,
                      float* __restrict__ C, int M, int N, int K)
{
    __shared__ float As[16][64];
    __shared__ float Bs[16][64];
    int tid = threadIdx.y * 16 + threadIdx.x;
    int rowBase = blockIdx.x * 64;
    int colBase = blockIdx.y * 64;
    float acc[4][4] = {};
    for (int k0 = 0; k0 < K; k0 += 16) {
        #pragma unroll
        for (int i = 0; i < 4; i++) {
            int idx = tid * 4 + i;
            int m  = idx >> 4;
            int kk = idx & 15;
            int gr = rowBase + m, gc = k0 + kk;
            As[kk][m] = (gr < M && gc < K) ? A[(size_t)gr * K + gc] : 0.0f;
        }
        #pragma unroll
        for (int i = 0; i < 4; i++) {
            int idx = tid * 4 + i;
            int kk = idx >> 6;
            int nn = idx & 63;
            int gr = k0 + kk, gc = colBase + nn;
            Bs[kk][nn] = (gr < K && gc < N) ? B[(size_t)gr * N + gc] : 0.0f;
        }
        __syncthreads();
        #pragma unroll
        for (int kk = 0; kk < 16; kk++) {
            float a[4], b[4];
            #pragma unroll
            for (int i = 0; i < 4; i++) a[i] = As[kk][threadIdx.y * 4 + i];
            #pragma unroll
            for (int j = 0; j < 4; j++) b[j] = Bs[kk][threadIdx.x * 4 + j];
            #pragma unroll
            for (int i = 0; i < 4; i++)
                #pragma unroll
                for (int j = 0; j < 4; j++) acc[i][j] += a[i] * b[j];
        }
        __syncthreads();
    }
    #pragma unroll
    for (int i = 0; i < 4; i++) {
        int gr = rowBase + threadIdx.y * 4 + i;
        if (gr >= M) continue;
        #pragma unroll
        for (int j = 0; j < 4; j++) {
            int gc = colBase + threadIdx.x * 4 + j;
            if (gc < N) C[(size_t)gr * N + gc] = acc[i][j];
        }
    }
}

// ---------------- attention scores (GAT2): warp per node ----------------------
template<int H, int C>
__global__ void att_scores_w(const float* __restrict__ h,
                             const float* __restrict__ a_src,
                             const float* __restrict__ a_dst,
                             float* __restrict__ es, float* __restrict__ ed, int n)
{
    const int HC = H * C;
    int gtid = blockIdx.x * blockDim.x + threadIdx.x;
    int node = gtid >> 5;
    int lane = threadIdx.x & 31;
    if (node >= n) return;
    const float4* row = (const float4*)(h + (size_t)node * HC);
    const float4* as4 = (const float4*)a_src;
    const float4* ad4 = (const float4*)a_dst;
    float accs[H], accd[H];
    #pragma unroll
    for (int hh = 0; hh < H; hh++) { accs[hh] = 0.0f; accd[hh] = 0.0f; }
    #pragma unroll
    for (int it = 0; it < HC / 128; it++) {
        int i4 = it * 32 + lane;
        float4 v = row[i4];
        int hh = i4 >> 4;
        float4 a = as4[hh * 16 + (i4 & 15)];
        float4 b = ad4[hh * 16 + (i4 & 15)];
        accs[hh] += v.x*a.x + v.y*a.y + v.z*a.z + v.w*a.w;
        accd[hh] += v.x*b.x + v.y*b.y + v.z*b.z + v.w*b.w;
    }
    #pragma unroll
    for (int hh = 0; hh < H; hh++) {
        #pragma unroll
        for (int off = 16; off; off >>= 1) {
            accs[hh] += __shfl_xor_sync(0xffffffffu, accs[hh], off);
            accd[hh] += __shfl_xor_sync(0xffffffffu, accd[hh], off);
        }
    }
    if (lane == 0) {
        #pragma unroll
        for (int hh = 0; hh < H; hh++) {
            es[node * H + hh] = accs[hh];
            ed[node * H + hh] = accd[hh];
        }
    }
}

// ---------------- fused GAT aggregation (block per dst node) ------------------
template<int H, int C>
__global__ void gat_fused(const float* __restrict__ h,
                          const float* __restrict__ es, const float* __restrict__ ed,
                          const float* __restrict__ b,
                          float* __restrict__ out, int n)
{
    const int HC = H * C;
    __shared__ int   srcs[MAXDEG];
    __shared__ float ebuf[MAXDEG * H];
    __shared__ float sh[H];

    int d   = blockIdx.x;
    int tid = threadIdx.x;
    int r0  = g_rp[d];
    int deg = g_rp[d + 1] - r0;
    if (r0 < 0) r0 = 0;
    if (deg < 0) deg = 0;
    if (deg > MAXDEG) deg = MAXDEG;
    if (r0 + deg > MAXET) deg = MAXET - r0 > 0 ? MAXET - r0 : 0;

    float edv[H];
    #pragma unroll
    for (int hh = 0; hh < H; hh++) edv[hh] = ed[d * H + hh];

    for (int j = tid; j < deg; j += HC) {
        int s = g_csr[r0 + j];
        srcs[j] = s;
        #pragma unroll
        for (int hh = 0; hh < H; hh++) {
            float v = es[s * H + hh] + edv[hh];
            v = v >= 0.0f ? v : 0.2f * v;
            ebuf[j * H + hh] = v;
        }
    }
    __syncthreads();

    int warp = tid >> 5, lane = tid & 31;
    if (warp < H) {
        int hh = warp;
        float m = -3.402823466e38f;
        for (int j = lane; j < deg; j += 32) m = fmaxf(m, ebuf[j * H + hh]);
        #pragma unroll
        for (int off = 16; off; off >>= 1)
            m = fmaxf(m, __shfl_xor_sync(0xffffffffu, m, off));
        float s = 0.0f;
        for (int j = lane; j < deg; j += 32) {
            float ex = __expf(ebuf[j * H + hh] - m);
            ebuf[j * H + hh] = ex;
            s += ex;
        }
        #pragma unroll
        for (int off = 16; off; off >>= 1)
            s += __shfl_xor_sync(0xffffffffu, s, off);
        if (lane == 0) sh[hh] = s;
    }
    __syncthreads();

    int c = tid;
    int hc = c / C;
    float acc = 0.0f;
    int j = 0;
    for (; j + 4 <= deg; j += 4) {
        float e0 = ebuf[(j + 0) * H + hc];
        float e1 = ebuf[(j + 1) * H + hc];
        float e2 = ebuf[(j + 2) * H + hc];
        float e3 = ebuf[(j + 3) * H + hc];
        float h0 = h[(size_t)srcs[j + 0] * HC + c];
        float h1 = h[(size_t)srcs[j + 1] * HC + c];
        float h2 = h[(size_t)srcs[j + 2] * HC + c];
        float h3 = h[(size_t)srcs[j + 3] * HC + c];
        acc += e0 * h0 + e1 * h1 + e2 * h2 + e3 * h3;
    }
    for (; j < deg; j++)
        acc += ebuf[j * H + hc] * h[(size_t)srcs[j] * HC + c];

    float o = acc / (sh[hc] + 1e-16f) + b[c];
    out[(size_t)d * HC + c] = o > 0.0f ? o : expm1f(o);
}

// ---------------- fused GCN aggregation ---------------------------------------
template<int F>
__global__ void gcn_fused(const float* __restrict__ h,
                          const float* __restrict__ dinv,
                          const float* __restrict__ b,
                          float* __restrict__ out, int n)
{
    const int G = 128 / F;
    int g = threadIdx.x / F, c = threadIdx.x % F;
    int d = blockIdx.x * G + g;
    if (d >= n) return;
    int r0 = g_rp[d], deg = g_rp[d + 1] - r0;
    if (r0 < 0) r0 = 0;
    if (deg < 0) deg = 0;
    if (r0 + deg > MAXET) deg = MAXET - r0 > 0 ? MAXET - r0 : 0;
    float acc = 0.0f;
    int j = 0;
    for (; j + 4 <= deg; j += 4) {
        int s0 = g_csr[r0 + j + 0];
        int s1 = g_csr[r0 + j + 1];
        int s2 = g_csr[r0 + j + 2];
        int s3 = g_csr[r0 + j + 3];
        acc += dinv[s0] * h[(size_t)s0 * F + c]
             + dinv[s1] * h[(size_t)s1 * F + c]
             + dinv[s2] * h[(size_t)s2 * F + c]
             + dinv[s3] * h[(size_t)s3 * F + c];
    }
    for (; j < deg; j++) {
        int s = g_csr[r0 + j];
        acc += dinv[s] * h[(size_t)s * F + c];
    }
    float o = dinv[d] * acc + b[c];
    out[(size_t)d * F + c] = o > 0.0f ? o : expm1f(o);
}

// ---------------- heads -------------------------------------------------------
__global__ void zone_head(const float* __restrict__ h, const float* __restrict__ Wz,
                          const float* __restrict__ bz, float* out, int n)
{
    int idx = blockIdx.x * blockDim.x + threadIdx.x;
    if (idx >= n * 4) return;
    int i = idx >> 2, j = idx & 3;
    float acc = bz[j];
    const float* row = h + (size_t)i * 32;
    #pragma unroll
    for (int k = 0; k < 32; k++) acc += row[k] * Wz[k * 4 + j];
    out[idx] = acc;
}

__global__ void zero_gsum() {
    if (threadIdx.x < 32) g_gsum[threadIdx.x] = 0.0f;
}

__global__ void mean_reduce(const float* __restrict__ h, int n)
{
    __shared__ float sm[256];
    int ch = threadIdx.x & 31;
    int grp = threadIdx.x >> 5;
    float acc = 0.0f;
    for (int r = blockIdx.x * 8 + grp; r < n; r += gridDim.x * 8)
        acc += h[(size_t)r * 32 + ch];
    sm[threadIdx.x] = acc;
    __syncthreads();
    if (grp == 0) {
        float t = 0.0f;
        #pragma unroll
        for (int g = 0; g < 8; g++) t += sm[g * 32 + ch];
        atomicAdd(&g_gsum[ch], t);
    }
}

__global__ void heads_kernel(const float* Ws, const float* bs,
                             const float* Wa, const float* ba,
                             const float* Wc, const float* bc,
                             float* out3, int n)
{
    int t = threadIdx.x;
    float mean = g_gsum[t] / (float)n;
    float vs = mean * Ws[t];
    float va = mean * Wa[t];
    float vc = mean * Wc[t];
    #pragma unroll
    for (int o = 16; o > 0; o >>= 1) {
        vs += __shfl_down_sync(0xffffffffu, vs, o);
        va += __shfl_down_sync(0xffffffffu, va, o);
        vc += __shfl_down_sync(0xffffffffu, vc, o);
    }
    if (t == 0) {
        out3[0] = 1.0f / (1.0f + expf(-(vs + bs[0])));
        out3[1] = 1.0f / (1.0f + expf(-(va + ba[0])));
        out3[2] = 1.0f / (1.0f + expf(-(vc + bc[0])));
    }
}

// ---------------- launch ------------------------------------------------------
extern "C" void kernel_launch(void* const* d_in, const int* in_sizes, int n_in,
                              void* d_out, int out_size)
{
    const float* x      = (const float*)d_in[0];
    const void*  ei     = d_in[1];
    const float* W1     = (const float*)d_in[2];
    const float* a1_src = (const float*)d_in[3];
    const float* a1_dst = (const float*)d_in[4];
    const float* b1     = (const float*)d_in[5];
    const float* W2     = (const float*)d_in[6];
    const float* a2_src = (const float*)d_in[7];
    const float* a2_dst = (const float*)d_in[8];
    const float* b2     = (const float*)d_in[9];
    const float* W3     = (const float*)d_in[10];
    const float* b3     = (const float*)d_in[11];
    const float* W4     = (const float*)d_in[12];
    const float* b4     = (const float*)d_in[13];
    const float* Wz     = (const float*)d_in[14];
    const float* bz     = (const float*)d_in[15];
    const float* Ws     = (const float*)d_in[16];
    const float* bs     = (const float*)d_in[17];
    const float* Wa     = (const float*)d_in[18];
    const float* ba     = (const float*)d_in[19];
    const float* Wc     = (const float*)d_in[20];
    const float* bc     = (const float*)d_in[21];

    int n = in_sizes[0] / 10;
    int E = in_sizes[1] / 2;
    int Etot = E + n;
    int nb = CDIV(n, SCAN_CHUNK);

    float* out      = (float*)d_out;
    float* out_zone = out;
    float* out_sc   = out + (size_t)n * 4;
    float* out_h    = out + (size_t)n * 4 + 3;

    float *p_o1, *p_h2, *p_o2, *p_g3, *p_o3, *p_g4, *p_es, *p_ed, *p_dinv;
    cudaGetSymbolAddress((void**)&p_o1,  g_o1);
    cudaGetSymbolAddress((void**)&p_h2,  g_h2);
    cudaGetSymbolAddress((void**)&p_o2,  g_o2);
    cudaGetSymbolAddress((void**)&p_g3,  g_g3);
    cudaGetSymbolAddress((void**)&p_o3,  g_o3);
    cudaGetSymbolAddress((void**)&p_g4,  g_g4);
    cudaGetSymbolAddress((void**)&p_es,  g_es);
    cudaGetSymbolAddress((void**)&p_ed,  g_ed);
    cudaGetSymbolAddress((void**)&p_dinv,g_dinv);

    const int T = 256;
    dim3 tb(16, 16);

    // ---- CSR build ----
    sniff_kernel<<<1, 1>>>(ei);
    zero_degi<<<CDIV(n, T), T>>>(n);
    decode_count<<<CDIV(Etot, T), T>>>(ei, E, n);
    scan_a<<<nb, 256>>>(n);
    scan_b<<<1, 32>>>(nb, n);
    scan_c<<<nb, 256>>>(n);
    scatter_csr<<<CDIV(Etot, T), T>>>(Etot);

    // ---- GAT1: aggregate x (10 ch), then project (h1 never materialized) ----
    proj_att1<<<1, 128>>>(W1, a1_src, a1_dst);
    att1_scores<<<CDIV(n, T), T>>>(x, n);
    gat1_agg<<<CDIV(n, 128), 128>>>(x, n);
    gat1_out<<<CDIV(n, 8), 256>>>(W1, b1, p_o1, n);

    // ---- GAT2: 256 -> H=2, C=64 ----
    sgemm128<<<dim3(CDIV(n, 128), 1), 256>>>(p_o1, W2, p_h2, n, 128, 256);
    att_scores_w<2, 64><<<CDIV(n * 32, T), T>>>(p_h2, a2_src, a2_dst, p_es, p_ed, n);
    gat_fused<2, 64><<<n, 128>>>(p_h2, p_es, p_ed, b2, p_o2, n);

    // ---- GCN1: 128 -> 64 ----
    sgemm<<<dim3(CDIV(n, 64), 1), tb>>>(p_o2, W3, p_g3, n, 64, 128);
    gcn_fused<64><<<CDIV(n, 2), 128>>>(p_g3, p_dinv, b3, p_o3, n);

    // ---- GCN2: 64 -> 32 ----
    sgemm<<<dim3(CDIV(n, 64), 1), tb>>>(p_o3, W4, p_g4, n, 32, 64);
    gcn_fused<32><<<CDIV(n, 4), 128>>>(p_g4, p_dinv, b4, out_h, n);

    // ---- heads ----
    zone_head<<<CDIV(n * 4, T), T>>>(out_h, Wz, bz, out_zone, n);
    zero_gsum<<<1, 32>>>();
    mean_reduce<<<128, 256>>>(out_h, n);
    heads_kernel<<<1, 32>>>(Ws, bs, Wa, ba, Wc, bc, out_sc, n);
}

// round 9
// speedup vs baseline: 4.1701x; 1.2562x over previous
#include <cuda_runtime.h>
#include <math.h>
#include <stdint.h>

#define MAXN 50000
#define MAXE 400000
#define MAXET (MAXN + MAXE)
#define CDIV(a,b) (((a)+(b)-1)/(b))
#define MAXDEG 512
#define SCAN_CHUNK 1024
#define MAXBLK 64

// ---------------- scratch ----------------------------------------------------
__device__ float g_xagg[MAXN*40];
__device__ float g_o1[MAXN*256];
__device__ float g_h2[MAXN*128];
__device__ float g_o2[MAXN*128];
__device__ float g_g3[MAXN*64];
__device__ float g_o3[MAXN*64];
__device__ float g_g4[MAXN*32];
__device__ float g_es[MAXN*4];
__device__ float g_ed[MAXN*4];
__device__ int   g_src[MAXET];
__device__ int   g_dst[MAXET];
__device__ int   g_degi[MAXN];
__device__ int   g_rp[MAXN+1];
__device__ int   g_woff[MAXN];
__device__ int   g_csr[MAXET];
__device__ float g_dinv[MAXN];
__device__ float g_gsum[32];
__device__ float g_ws1[40];
__device__ float g_wd1[40];
__device__ int   g_bsum[MAXBLK];
__device__ int   g_boff[MAXBLK];
__device__ int   g_is64;

// ---------------- dtype sniff + fused edge decode + degree count --------------
__global__ void sniff_kernel(const void* ei) {
    const int* r = (const int*)ei;
    int is64 = 1;
    for (int k = 0; k < 128; k++)
        if (r[2*k + 1] != 0) { is64 = 0; break; }
    g_is64 = is64;
}

__global__ void zero_degi(int n) {
    int i = blockIdx.x * blockDim.x + threadIdx.x;
    if (i < n) g_degi[i] = 0;
}

__global__ void decode_count(const void* ei, int E, int n) {
    int e = blockIdx.x * blockDim.x + threadIdx.x;
    int Etot = E + n;
    if (e >= Etot) return;
    int s, d;
    if (e < E) {
        if (g_is64) {
            const long long* p = (const long long*)ei;
            s = (int)p[e];
            d = (int)p[(size_t)E + e];
        } else {
            const int* p = (const int*)ei;
            s = p[e];
            d = p[E + e];
        }
    } else {
        s = e - E;
        d = e - E;
    }
    s = s < 0 ? 0 : (s >= n ? n - 1 : s);
    d = d < 0 ? 0 : (d >= n ? n - 1 : d);
    g_src[e] = s;
    g_dst[e] = d;
    atomicAdd(&g_degi[d], 1);
}

// ---------------- 3-phase multi-block exclusive scan ---------------------------
__global__ void scan_a(int n) {
    __shared__ int wsum[8];
    int b = blockIdx.x;
    int base = b * SCAN_CHUNK;
    int tid = threadIdx.x;
    int s = 0;
    #pragma unroll
    for (int q = 0; q < 4; q++) {
        int i = base + tid * 4 + q;
        if (i < n) s += g_degi[i];
    }
    #pragma unroll
    for (int off = 16; off; off >>= 1) s += __shfl_xor_sync(0xffffffffu, s, off);
    if ((tid & 31) == 0) wsum[tid >> 5] = s;
    __syncthreads();
    if (tid == 0) {
        int t = 0;
        #pragma unroll
        for (int w = 0; w < 8; w++) t += wsum[w];
        g_bsum[b] = t;
    }
}

__global__ void scan_b(int nb, int n) {
    int lane = threadIdx.x;
    int v0 = (2 * lane     < nb) ? g_bsum[2 * lane]     : 0;
    int v1 = (2 * lane + 1 < nb) ? g_bsum[2 * lane + 1] : 0;
    int s = v0 + v1;
    int inc = s;
    #pragma unroll
    for (int off = 1; off < 32; off <<= 1) {
        int t = __shfl_up_sync(0xffffffffu, inc, off);
        if (lane >= off) inc += t;
    }
    int excl = inc - s;
    if (2 * lane     < nb) g_boff[2 * lane]     = excl;
    if (2 * lane + 1 < nb) g_boff[2 * lane + 1] = excl + v0;
    if (lane == 31) g_rp[n] = inc;
}

__global__ void scan_c(int n) {
    __shared__ int woffs[8];
    int b = blockIdx.x;
    int base = b * SCAN_CHUNK;
    int tid = threadIdx.x;
    int lane = tid & 31, w = tid >> 5;
    int d[4];
    int s = 0;
    #pragma unroll
    for (int q = 0; q < 4; q++) {
        int i = base + tid * 4 + q;
        d[q] = (i < n) ? g_degi[i] : 0;
        s += d[q];
    }
    int inc = s;
    #pragma unroll
    for (int off = 1; off < 32; off <<= 1) {
        int t = __shfl_up_sync(0xffffffffu, inc, off);
        if (lane >= off) inc += t;
    }
    if (lane == 31) woffs[w] = inc;
    __syncthreads();
    if (tid == 0) {
        int run = 0;
        #pragma unroll
        for (int i = 0; i < 8; i++) { int t = woffs[i]; woffs[i] = run; run += t; }
    }
    __syncthreads();
    int excl = inc - s + woffs[w] + g_boff[b];
    #pragma unroll
    for (int q = 0; q < 4; q++) {
        int i = base + tid * 4 + q;
        if (i < n) {
            g_rp[i] = excl;
            g_woff[i] = excl;
            excl += d[q];
            g_dinv[i] = rsqrtf(fmaxf((float)d[q], 1e-12f));
        }
    }
}

__global__ void scatter_csr(int Etot) {
    int e = blockIdx.x * blockDim.x + threadIdx.x;
    if (e >= Etot) return;
    int d = g_dst[e];
    int pos = atomicAdd(&g_woff[d], 1);
    if (pos >= 0 && pos < MAXET) g_csr[pos] = g_src[e];
}

// ---------------- GAT1: projected attention vectors ---------------------------
__global__ void proj_att1(const float* __restrict__ W1,
                          const float* __restrict__ a1s,
                          const float* __restrict__ a1d) {
    int t = threadIdx.x;
    if (t >= 80) return;
    int which = t / 40;
    int r = t % 40;
    int k = r / 4, h = r % 4;
    const float* a = which ? a1d : a1s;
    float s = 0.0f;
    for (int c = 0; c < 64; c++) s += W1[k * 256 + h * 64 + c] * a[h * 64 + c];
    if (which) g_wd1[k * 4 + h] = s; else g_ws1[k * 4 + h] = s;
}

__global__ void att1_scores(const float* __restrict__ x, int n) {
    int i = blockIdx.x * blockDim.x + threadIdx.x;
    if (i >= n) return;
    float xr[10];
    #pragma unroll
    for (int k = 0; k < 10; k++) xr[k] = x[(size_t)i * 10 + k];
    #pragma unroll
    for (int h = 0; h < 4; h++) {
        float s1 = 0.0f, s2 = 0.0f;
        #pragma unroll
        for (int k = 0; k < 10; k++) {
            s1 += xr[k] * g_ws1[k * 4 + h];
            s2 += xr[k] * g_wd1[k * 4 + h];
        }
        g_es[i * 4 + h] = s1;
        g_ed[i * 4 + h] = s2;
    }
}

// 4 threads per node: one per head (better MLP on the gather chains)
__global__ void gat1_agg(const float* __restrict__ x, int n) {
    int t = blockIdx.x * blockDim.x + threadIdx.x;
    int d = t >> 2, h = t & 3;
    if (d >= n) return;
    int r0 = g_rp[d];
    int deg = g_rp[d + 1] - r0;
    if (r0 < 0) r0 = 0;
    if (deg < 0) deg = 0;
    if (r0 + deg > MAXET) deg = MAXET - r0 > 0 ? MAXET - r0 : 0;

    float edv = g_ed[d * 4 + h];

    float m = -3.402823466e38f;
    for (int j = 0; j < deg; j++) {
        int s = g_csr[r0 + j];
        float v = g_es[s * 4 + h] + edv;
        v = v >= 0.0f ? v : 0.2f * v;
        m = fmaxf(m, v);
    }
    float ssum = 0.0f;
    float acc[10];
    #pragma unroll
    for (int k = 0; k < 10; k++) acc[k] = 0.0f;
    for (int j = 0; j < deg; j++) {
        int s = g_csr[r0 + j];
        float v = g_es[s * 4 + h] + edv;
        v = v >= 0.0f ? v : 0.2f * v;
        float ex = __expf(v - m);
        ssum += ex;
        const float* xr = x + (size_t)s * 10;
        #pragma unroll
        for (int k = 0; k < 10; k++) acc[k] += ex * xr[k];
    }
    float inv = 1.0f / (ssum + 1e-16f);
    #pragma unroll
    for (int k = 0; k < 10; k++)
        g_xagg[(size_t)d * 40 + h * 10 + k] = acc[k] * inv;
}

__global__ void gat1_out(const float* __restrict__ W1, const float* __restrict__ b1,
                         float* __restrict__ out, int n) {
    __shared__ float xs[8][40];
    int c = threadIdx.x;
    int row0 = blockIdx.x * 8;
    int h = c >> 6;
    float w[10];
    #pragma unroll
    for (int k = 0; k < 10; k++) w[k] = W1[k * 256 + c];
    for (int t = threadIdx.x; t < 8 * 40; t += 256) {
        int r = t / 40, k = t - r * 40;
        int gr = row0 + r;
        xs[r][k] = (gr < n) ? g_xagg[(size_t)gr * 40 + k] : 0.0f;
    }
    __syncthreads();
    float bc = b1[c];
    for (int r = 0; r < 8; r++) {
        int gr = row0 + r;
        if (gr >= n) break;
        float acc = 0.0f;
        #pragma unroll
        for (int k = 0; k < 10; k++) acc += xs[r][h * 10 + k] * w[k];
        float o = acc + bc;
        out[(size_t)gr * 256 + c] = o > 0.0f ? o : expm1f(o);
    }
}

// ---------------- tf32 tensor-core GEMM: C[M,N] = A[M,K] @ B[K,N] -------------
// block tile 128x128, 256 threads = 8 warps (4 m x 2 n), warp tile 32x64.
// K must be a multiple of 16. N <= 128 per grid.y tile (cols >= N zero-padded).
__device__ __forceinline__ uint32_t f2tf32(float f) {
    uint32_t r;
    asm("cvt.rna.tf32.f32 %0, %1;" : "=r"(r) : "f"(f));
    return r;
}

__device__ __forceinline__ void mma_tf32(float* c, const uint32_t* a,
                                         uint32_t b0, uint32_t b1) {
    asm volatile(
        "mma.sync.aligned.m16n8k8.row.col.f32.tf32.tf32.f32 "
        "{%0,%1,%2,%3}, {%4,%5,%6,%7}, {%8,%9}, {%0,%1,%2,%3};"
        : "+f"(c[0]), "+f"(c[1]), "+f"(c[2]), "+f"(c[3])
        : "r"(a[0]), "r"(a[1]), "r"(a[2]), "r"(a[3]), "r"(b0), "r"(b1));
}

__global__ void sgemm_tf32(const float* __restrict__ A, const float* __restrict__ B,
                           float* __restrict__ C, int M, int N, int K)
{
    __shared__ float As[16][132];   // tf32 bit-patterns stored as float
    __shared__ float Bs[16][132];
    int tid = threadIdx.x;
    int lane = tid & 31, warp = tid >> 5;
    int warp_m = warp & 3, warp_n = warp >> 2;
    int grp = lane >> 2, tig = lane & 3;
    int rowBase = blockIdx.x * 128;
    int colBase = blockIdx.y * 128;

    float c[2][8][4];
    #pragma unroll
    for (int sm = 0; sm < 2; sm++)
        #pragma unroll
        for (int n8 = 0; n8 < 8; n8++)
            #pragma unroll
            for (int q = 0; q < 4; q++) c[sm][n8][q] = 0.0f;

    for (int k0 = 0; k0 < K; k0 += 16) {
        #pragma unroll
        for (int q = 0; q < 2; q++) {
            int idx = tid * 2 + q;               // 0..511
            int m = idx >> 2, kq = (idx & 3) * 4;
            int gr = rowBase + m;
            float4 v = make_float4(0.f, 0.f, 0.f, 0.f);
            if (gr < M) v = *(const float4*)(A + (size_t)gr * K + k0 + kq);
            As[kq + 0][m] = __uint_as_float(f2tf32(v.x));
            As[kq + 1][m] = __uint_as_float(f2tf32(v.y));
            As[kq + 2][m] = __uint_as_float(f2tf32(v.z));
            As[kq + 3][m] = __uint_as_float(f2tf32(v.w));
        }
        #pragma unroll
        for (int q = 0; q < 2; q++) {
            int idx = tid * 2 + q;
            int kk = idx >> 5, n4 = (idx & 31) * 4;
            int gc = colBase + n4;
            float4 v = make_float4(0.f, 0.f, 0.f, 0.f);
            if (gc + 3 < N) v = *(const float4*)(B + (size_t)(k0 + kk) * N + gc);
            Bs[kk][n4 + 0] = __uint_as_float(f2tf32(v.x));
            Bs[kk][n4 + 1] = __uint_as_float(f2tf32(v.y));
            Bs[kk][n4 + 2] = __uint_as_float(f2tf32(v.z));
            Bs[kk][n4 + 3] = __uint_as_float(f2tf32(v.w));
        }
        __syncthreads();
        #pragma unroll
        for (int kc = 0; kc < 16; kc += 8) {
            uint32_t afr[2][4];
            #pragma unroll
            for (int sm = 0; sm < 2; sm++) {
                int r = warp_m * 32 + sm * 16;
                afr[sm][0] = __float_as_uint(As[kc + tig    ][r + grp    ]);
                afr[sm][1] = __float_as_uint(As[kc + tig    ][r + grp + 8]);
                afr[sm][2] = __float_as_uint(As[kc + tig + 4][r + grp    ]);
                afr[sm][3] = __float_as_uint(As[kc + tig + 4][r + grp + 8]);
            }
            #pragma unroll
            for (int n8 = 0; n8 < 8; n8++) {
                int cb = warp_n * 64 + n8 * 8;
                uint32_t b0 = __float_as_uint(Bs[kc + tig    ][cb + grp]);
                uint32_t b1 = __float_as_uint(Bs[kc + tig + 4][cb + grp]);
                mma_tf32(c[0][n8], afr[0], b0, b1);
                mma_tf32(c[1][n8], afr[1], b0, b1);
            }
        }
        __syncthreads();
    }

    #pragma unroll
    for (int sm = 0; sm < 2; sm++) {
        int r0 = rowBase + warp_m * 32 + sm * 16 + grp;
        #pragma unroll
        for (int n8 = 0; n8 < 8; n8++) {
            int c0 = colBase + warp_n * 64 + n8 * 8 + tig * 2;
            if (r0 < M && c0 + 1 < N) {
                C[(size_t)r0 * N + c0    ] = c[sm][n8][0];
                C[(size_t)r0 * N + c0 + 1] = c[sm][n8][1];
            }
            if (r0 + 8 < M && c0 + 1 < N) {
                C[(size_t)(r0 + 8) * N + c0    ] = c[sm][n8][2];
                C[(size_t)(r0 + 8) * N + c0 + 1] = c[sm][n8][3];
            }
        }
    }
}

// ---------------- generic 64-tile SGEMM (GCN2 only) ---------------------------
__global__ void sgemm(const float* __restrict__ A, const float* __restrict__ B,
                      float* __restrict__ C, int M, int N, int K)
{
    __shared__ float As[16][64];
    __shared__ float Bs[16][64];
    int tid = threadIdx.y * 16 + threadIdx.x;
    int rowBase = blockIdx.x * 64;
    int colBase = blockIdx.y * 64;
    float acc[4][4] = {};
    for (int k0 = 0; k0 < K; k0 += 16) {
        #pragma unroll
        for (int i = 0; i < 4; i++) {
            int idx = tid * 4 + i;
            int m  = idx >> 4;
            int kk = idx & 15;
            int gr = rowBase + m, gc = k0 + kk;
            As[kk][m] = (gr < M && gc < K) ? A[(size_t)gr * K + gc] : 0.0f;
        }
        #pragma unroll
        for (int i = 0; i < 4; i++) {
            int idx = tid * 4 + i;
            int kk = idx >> 6;
            int nn = idx & 63;
            int gr = k0 + kk, gc = colBase + nn;
            Bs[kk][nn] = (gr < K && gc < N) ? B[(size_t)gr * N + gc] : 0.0f;
        }
        __syncthreads();
        #pragma unroll
        for (int kk = 0; kk < 16; kk++) {
            float a[4], b[4];
            #pragma unroll
            for (int i = 0; i < 4; i++) a[i] = As[kk][threadIdx.y * 4 + i];
            #pragma unroll
            for (int j = 0; j < 4; j++) b[j] = Bs[kk][threadIdx.x * 4 + j];
            #pragma unroll
            for (int i = 0; i < 4; i++)
                #pragma unroll
                for (int j = 0; j < 4; j++) acc[i][j] += a[i] * b[j];
        }
        __syncthreads();
    }
    #pragma unroll
    for (int i = 0; i < 4; i++) {
        int gr = rowBase + threadIdx.y * 4 + i;
        if (gr >= M) continue;
        #pragma unroll
        for (int j = 0; j < 4; j++) {
            int gc = colBase + threadIdx.x * 4 + j;
            if (gc < N) C[(size_t)gr * N + gc] = acc[i][j];
        }
    }
}

// ---------------- attention scores (GAT2): warp per node ----------------------
template<int H, int C>
__global__ void att_scores_w(const float* __restrict__ h,
                             const float* __restrict__ a_src,
                             const float* __restrict__ a_dst,
                             float* __restrict__ es, float* __restrict__ ed, int n)
{
    const int HC = H * C;
    int gtid = blockIdx.x * blockDim.x + threadIdx.x;
    int node = gtid >> 5;
    int lane = threadIdx.x & 31;
    if (node >= n) return;
    const float4* row = (const float4*)(h + (size_t)node * HC);
    const float4* as4 = (const float4*)a_src;
    const float4* ad4 = (const float4*)a_dst;
    float accs[H], accd[H];
    #pragma unroll
    for (int hh = 0; hh < H; hh++) { accs[hh] = 0.0f; accd[hh] = 0.0f; }
    #pragma unroll
    for (int it = 0; it < HC / 128; it++) {
        int i4 = it * 32 + lane;
        float4 v = row[i4];
        int hh = i4 >> 4;
        float4 a = as4[hh * 16 + (i4 & 15)];
        float4 b = ad4[hh * 16 + (i4 & 15)];
        accs[hh] += v.x*a.x + v.y*a.y + v.z*a.z + v.w*a.w;
        accd[hh] += v.x*b.x + v.y*b.y + v.z*b.z + v.w*b.w;
    }
    #pragma unroll
    for (int hh = 0; hh < H; hh++) {
        #pragma unroll
        for (int off = 16; off; off >>= 1) {
            accs[hh] += __shfl_xor_sync(0xffffffffu, accs[hh], off);
            accd[hh] += __shfl_xor_sync(0xffffffffu, accd[hh], off);
        }
    }
    if (lane == 0) {
        #pragma unroll
        for (int hh = 0; hh < H; hh++) {
            es[node * H + hh] = accs[hh];
            ed[node * H + hh] = accd[hh];
        }
    }
}

// ---------------- fused GAT aggregation (block per dst node) ------------------
template<int H, int C>
__global__ void gat_fused(const float* __restrict__ h,
                          const float* __restrict__ es, const float* __restrict__ ed,
                          const float* __restrict__ b,
                          float* __restrict__ out, int n)
{
    const int HC = H * C;
    __shared__ int   srcs[MAXDEG];
    __shared__ float ebuf[MAXDEG * H];
    __shared__ float sh[H];

    int d   = blockIdx.x;
    int tid = threadIdx.x;
    int r0  = g_rp[d];
    int deg = g_rp[d + 1] - r0;
    if (r0 < 0) r0 = 0;
    if (deg < 0) deg = 0;
    if (deg > MAXDEG) deg = MAXDEG;
    if (r0 + deg > MAXET) deg = MAXET - r0 > 0 ? MAXET - r0 : 0;

    float edv[H];
    #pragma unroll
    for (int hh = 0; hh < H; hh++) edv[hh] = ed[d * H + hh];

    for (int j = tid; j < deg; j += HC) {
        int s = g_csr[r0 + j];
        srcs[j] = s;
        #pragma unroll
        for (int hh = 0; hh < H; hh++) {
            float v = es[s * H + hh] + edv[hh];
            v = v >= 0.0f ? v : 0.2f * v;
            ebuf[j * H + hh] = v;
        }
    }
    __syncthreads();

    int warp = tid >> 5, lane = tid & 31;
    if (warp < H) {
        int hh = warp;
        float m = -3.402823466e38f;
        for (int j = lane; j < deg; j += 32) m = fmaxf(m, ebuf[j * H + hh]);
        #pragma unroll
        for (int off = 16; off; off >>= 1)
            m = fmaxf(m, __shfl_xor_sync(0xffffffffu, m, off));
        float s = 0.0f;
        for (int j = lane; j < deg; j += 32) {
            float ex = __expf(ebuf[j * H + hh] - m);
            ebuf[j * H + hh] = ex;
            s += ex;
        }
        #pragma unroll
        for (int off = 16; off; off >>= 1)
            s += __shfl_xor_sync(0xffffffffu, s, off);
        if (lane == 0) sh[hh] = s;
    }
    __syncthreads();

    int c = tid;
    int hc = c / C;
    float acc = 0.0f;
    int j = 0;
    for (; j + 4 <= deg; j += 4) {
        float e0 = ebuf[(j + 0) * H + hc];
        float e1 = ebuf[(j + 1) * H + hc];
        float e2 = ebuf[(j + 2) * H + hc];
        float e3 = ebuf[(j + 3) * H + hc];
        float h0 = h[(size_t)srcs[j + 0] * HC + c];
        float h1 = h[(size_t)srcs[j + 1] * HC + c];
        float h2 = h[(size_t)srcs[j + 2] * HC + c];
        float h3 = h[(size_t)srcs[j + 3] * HC + c];
        acc += e0 * h0 + e1 * h1 + e2 * h2 + e3 * h3;
    }
    for (; j < deg; j++)
        acc += ebuf[j * H + hc] * h[(size_t)srcs[j] * HC + c];

    float o = acc / (sh[hc] + 1e-16f) + b[c];
    out[(size_t)d * HC + c] = o > 0.0f ? o : expm1f(o);
}

// ---------------- fused GCN aggregation ---------------------------------------
template<int F>
__global__ void gcn_fused(const float* __restrict__ h,
                          const float* __restrict__ dinv,
                          const float* __restrict__ b,
                          float* __restrict__ out, int n)
{
    const int G = 128 / F;
    int g = threadIdx.x / F, c = threadIdx.x % F;
    int d = blockIdx.x * G + g;
    if (d >= n) return;
    int r0 = g_rp[d], deg = g_rp[d + 1] - r0;
    if (r0 < 0) r0 = 0;
    if (deg < 0) deg = 0;
    if (r0 + deg > MAXET) deg = MAXET - r0 > 0 ? MAXET - r0 : 0;
    float acc = 0.0f;
    int j = 0;
    for (; j + 4 <= deg; j += 4) {
        int s0 = g_csr[r0 + j + 0];
        int s1 = g_csr[r0 + j + 1];
        int s2 = g_csr[r0 + j + 2];
        int s3 = g_csr[r0 + j + 3];
        acc += dinv[s0] * h[(size_t)s0 * F + c]
             + dinv[s1] * h[(size_t)s1 * F + c]
             + dinv[s2] * h[(size_t)s2 * F + c]
             + dinv[s3] * h[(size_t)s3 * F + c];
    }
    for (; j < deg; j++) {
        int s = g_csr[r0 + j];
        acc += dinv[s] * h[(size_t)s * F + c];
    }
    float o = dinv[d] * acc + b[c];
    out[(size_t)d * F + c] = o > 0.0f ? o : expm1f(o);
}

// ---------------- heads -------------------------------------------------------
__global__ void zone_head(const float* __restrict__ h, const float* __restrict__ Wz,
                          const float* __restrict__ bz, float* out, int n)
{
    int idx = blockIdx.x * blockDim.x + threadIdx.x;
    if (idx >= n * 4) return;
    int i = idx >> 2, j = idx & 3;
    float acc = bz[j];
    const float* row = h + (size_t)i * 32;
    #pragma unroll
    for (int k = 0; k < 32; k++) acc += row[k] * Wz[k * 4 + j];
    out[idx] = acc;
}

__global__ void zero_gsum() {
    if (threadIdx.x < 32) g_gsum[threadIdx.x] = 0.0f;
}

__global__ void mean_reduce(const float* __restrict__ h, int n)
{
    __shared__ float sm[256];
    int ch = threadIdx.x & 31;
    int grp = threadIdx.x >> 5;
    float acc = 0.0f;
    for (int r = blockIdx.x * 8 + grp; r < n; r += gridDim.x * 8)
        acc += h[(size_t)r * 32 + ch];
    sm[threadIdx.x] = acc;
    __syncthreads();
    if (grp == 0) {
        float t = 0.0f;
        #pragma unroll
        for (int g = 0; g < 8; g++) t += sm[g * 32 + ch];
        atomicAdd(&g_gsum[ch], t);
    }
}

__global__ void heads_kernel(const float* Ws, const float* bs,
                             const float* Wa, const float* ba,
                             const float* Wc, const float* bc,
                             float* out3, int n)
{
    int t = threadIdx.x;
    float mean = g_gsum[t] / (float)n;
    float vs = mean * Ws[t];
    float va = mean * Wa[t];
    float vc = mean * Wc[t];
    #pragma unroll
    for (int o = 16; o > 0; o >>= 1) {
        vs += __shfl_down_sync(0xffffffffu, vs, o);
        va += __shfl_down_sync(0xffffffffu, va, o);
        vc += __shfl_down_sync(0xffffffffu, vc, o);
    }
    if (t == 0) {
        out3[0] = 1.0f / (1.0f + expf(-(vs + bs[0])));
        out3[1] = 1.0f / (1.0f + expf(-(va + ba[0])));
        out3[2] = 1.0f / (1.0f + expf(-(vc + bc[0])));
    }
}

// ---------------- launch ------------------------------------------------------
extern "C" void kernel_launch(void* const* d_in, const int* in_sizes, int n_in,
                              void* d_out, int out_size)
{
    const float* x      = (const float*)d_in[0];
    const void*  ei     = d_in[1];
    const float* W1     = (const float*)d_in[2];
    const float* a1_src = (const float*)d_in[3];
    const float* a1_dst = (const float*)d_in[4];
    const float* b1     = (const float*)d_in[5];
    const float* W2     = (const float*)d_in[6];
    const float* a2_src = (const float*)d_in[7];
    const float* a2_dst = (const float*)d_in[8];
    const float* b2     = (const float*)d_in[9];
    const float* W3     = (const float*)d_in[10];
    const float* b3     = (const float*)d_in[11];
    const float* W4     = (const float*)d_in[12];
    const float* b4     = (const float*)d_in[13];
    const float* Wz     = (const float*)d_in[14];
    const float* bz     = (const float*)d_in[15];
    const float* Ws     = (const float*)d_in[16];
    const float* bs     = (const float*)d_in[17];
    const float* Wa     = (const float*)d_in[18];
    const float* ba     = (const float*)d_in[19];
    const float* Wc     = (const float*)d_in[20];
    const float* bc     = (const float*)d_in[21];

    int n = in_sizes[0] / 10;
    int E = in_sizes[1] / 2;
    int Etot = E + n;
    int nb = CDIV(n, SCAN_CHUNK);

    float* out      = (float*)d_out;
    float* out_zone = out;
    float* out_sc   = out + (size_t)n * 4;
    float* out_h    = out + (size_t)n * 4 + 3;

    float *p_o1, *p_h2, *p_o2, *p_g3, *p_o3, *p_g4, *p_es, *p_ed, *p_dinv;
    cudaGetSymbolAddress((void**)&p_o1,  g_o1);
    cudaGetSymbolAddress((void**)&p_h2,  g_h2);
    cudaGetSymbolAddress((void**)&p_o2,  g_o2);
    cudaGetSymbolAddress((void**)&p_g3,  g_g3);
    cudaGetSymbolAddress((void**)&p_o3,  g_o3);
    cudaGetSymbolAddress((void**)&p_g4,  g_g4);
    cudaGetSymbolAddress((void**)&p_es,  g_es);
    cudaGetSymbolAddress((void**)&p_ed,  g_ed);
    cudaGetSymbolAddress((void**)&p_dinv,g_dinv);

    const int T = 256;
    dim3 tb(16, 16);

    // ---- CSR build ----
    sniff_kernel<<<1, 1>>>(ei);
    zero_degi<<<CDIV(n, T), T>>>(n);
    decode_count<<<CDIV(Etot, T), T>>>(ei, E, n);
    scan_a<<<nb, 256>>>(n);
    scan_b<<<1, 32>>>(nb, n);
    scan_c<<<nb, 256>>>(n);
    scatter_csr<<<CDIV(Etot, T), T>>>(Etot);

    // ---- GAT1: aggregate x (10 ch), then project (h1 never materialized) ----
    proj_att1<<<1, 128>>>(W1, a1_src, a1_dst);
    att1_scores<<<CDIV(n, T), T>>>(x, n);
    gat1_agg<<<CDIV(n * 4, 128), 128>>>(x, n);
    gat1_out<<<CDIV(n, 8), 256>>>(W1, b1, p_o1, n);

    // ---- GAT2: 256 -> H=2, C=64 (tf32 tensor-core GEMM) ----
    sgemm_tf32<<<dim3(CDIV(n, 128), 1), 256>>>(p_o1, W2, p_h2, n, 128, 256);
    att_scores_w<2, 64><<<CDIV(n * 32, T), T>>>(p_h2, a2_src, a2_dst, p_es, p_ed, n);
    gat_fused<2, 64><<<n, 128>>>(p_h2, p_es, p_ed, b2, p_o2, n);

    // ---- GCN1: 128 -> 64 (tf32 tensor-core GEMM) ----
    sgemm_tf32<<<dim3(CDIV(n, 128), 1), 256>>>(p_o2, W3, p_g3, n, 64, 128);
    gcn_fused<64><<<CDIV(n, 2), 128>>>(p_g3, p_dinv, b3, p_o3, n);

    // ---- GCN2: 64 -> 32 ----
    sgemm<<<dim3(CDIV(n, 64), 1), tb>>>(p_o3, W4, p_g4, n, 32, 64);
    gcn_fused<32><<<CDIV(n, 4), 128>>>(p_g4, p_dinv, b4, out_h, n);

    // ---- heads ----
    zone_head<<<CDIV(n * 4, T), T>>>(out_h, Wz, bz, out_zone, n);
    zero_gsum<<<1, 32>>>();
    mean_reduce<<<128, 256>>>(out_h, n);
    heads_kernel<<<1, 32>>>(Ws, bs, Wa, ba, Wc, bc, out_sc, n);
}

// round 10
// speedup vs baseline: 4.4720x; 1.0724x over previous
#include <cuda_runtime.h>
#include <math.h>
#include <stdint.h>

#define MAXN 50000
#define MAXE 400000
#define MAXET (MAXN + MAXE)
#define CDIV(a,b) (((a)+(b)-1)/(b))
#define SCAN_CHUNK 1024
#define MAXBLK 64

// ---------------- scratch ----------------------------------------------------
__device__ float g_xagg[MAXN*40];
__device__ float g_o1[MAXN*256];
__device__ float g_h2[MAXN*128];
__device__ float g_o2[MAXN*128];
__device__ float g_g3[MAXN*64];
__device__ float g_o3[MAXN*64];
__device__ float g_g4[MAXN*32];
__device__ float g_es[MAXN*4];
__device__ float g_ed[MAXN*4];
__device__ int   g_src[MAXET];
__device__ int   g_dst[MAXET];
__device__ int   g_degi[MAXN];
__device__ int   g_rp[MAXN+1];
__device__ int   g_woff[MAXN];
__device__ int   g_csr[MAXET];
__device__ float g_dinv[MAXN];
__device__ float g_gsum[32];
__device__ float g_ws1[40];
__device__ float g_wd1[40];
__device__ int   g_bsum[MAXBLK];
__device__ int   g_boff[MAXBLK];
__device__ int   g_is64;

// ---------------- parallel dtype sniff ----------------------------------------
__global__ void sniff_kernel(const void* ei) {
    int t = threadIdx.x;  // 128
    int nz = ((const int*)ei)[2 * t + 1] != 0;
    unsigned m = __ballot_sync(0xffffffffu, nz);
    __shared__ unsigned s[4];
    if ((t & 31) == 0) s[t >> 5] = m;
    __syncthreads();
    if (t == 0) g_is64 = ((s[0] | s[1] | s[2] | s[3]) == 0) ? 1 : 0;
}

__global__ void zero_degi(int n) {
    int i = blockIdx.x * blockDim.x + threadIdx.x;
    if (i < n) g_degi[i] = 0;
}

__global__ void decode_count(const void* ei, int E, int n) {
    int e = blockIdx.x * blockDim.x + threadIdx.x;
    int Etot = E + n;
    if (e >= Etot) return;
    int s, d;
    if (e < E) {
        if (g_is64) {
            const long long* p = (const long long*)ei;
            s = (int)p[e];
            d = (int)p[(size_t)E + e];
        } else {
            const int* p = (const int*)ei;
            s = p[e];
            d = p[E + e];
        }
    } else {
        s = e - E;
        d = e - E;
    }
    s = s < 0 ? 0 : (s >= n ? n - 1 : s);
    d = d < 0 ? 0 : (d >= n ? n - 1 : d);
    g_src[e] = s;
    g_dst[e] = d;
    atomicAdd(&g_degi[d], 1);
}

// ---------------- 3-phase multi-block exclusive scan ---------------------------
__global__ void scan_a(int n) {
    __shared__ int wsum[8];
    int b = blockIdx.x;
    int base = b * SCAN_CHUNK;
    int tid = threadIdx.x;
    int s = 0;
    #pragma unroll
    for (int q = 0; q < 4; q++) {
        int i = base + tid * 4 + q;
        if (i < n) s += g_degi[i];
    }
    #pragma unroll
    for (int off = 16; off; off >>= 1) s += __shfl_xor_sync(0xffffffffu, s, off);
    if ((tid & 31) == 0) wsum[tid >> 5] = s;
    __syncthreads();
    if (tid == 0) {
        int t = 0;
        #pragma unroll
        for (int w = 0; w < 8; w++) t += wsum[w];
        g_bsum[b] = t;
    }
}

__global__ void scan_b(int nb, int n) {
    int lane = threadIdx.x;
    int v0 = (2 * lane     < nb) ? g_bsum[2 * lane]     : 0;
    int v1 = (2 * lane + 1 < nb) ? g_bsum[2 * lane + 1] : 0;
    int s = v0 + v1;
    int inc = s;
    #pragma unroll
    for (int off = 1; off < 32; off <<= 1) {
        int t = __shfl_up_sync(0xffffffffu, inc, off);
        if (lane >= off) inc += t;
    }
    int excl = inc - s;
    if (2 * lane     < nb) g_boff[2 * lane]     = excl;
    if (2 * lane + 1 < nb) g_boff[2 * lane + 1] = excl + v0;
    if (lane == 31) g_rp[n] = inc;
}

__global__ void scan_c(int n) {
    __shared__ int woffs[8];
    int b = blockIdx.x;
    int base = b * SCAN_CHUNK;
    int tid = threadIdx.x;
    int lane = tid & 31, w = tid >> 5;
    int d[4];
    int s = 0;
    #pragma unroll
    for (int q = 0; q < 4; q++) {
        int i = base + tid * 4 + q;
        d[q] = (i < n) ? g_degi[i] : 0;
        s += d[q];
    }
    int inc = s;
    #pragma unroll
    for (int off = 1; off < 32; off <<= 1) {
        int t = __shfl_up_sync(0xffffffffu, inc, off);
        if (lane >= off) inc += t;
    }
    if (lane == 31) woffs[w] = inc;
    __syncthreads();
    if (tid == 0) {
        int run = 0;
        #pragma unroll
        for (int i = 0; i < 8; i++) { int t = woffs[i]; woffs[i] = run; run += t; }
    }
    __syncthreads();
    int excl = inc - s + woffs[w] + g_boff[b];
    #pragma unroll
    for (int q = 0; q < 4; q++) {
        int i = base + tid * 4 + q;
        if (i < n) {
            g_rp[i] = excl;
            g_woff[i] = excl;
            excl += d[q];
            g_dinv[i] = rsqrtf(fmaxf((float)d[q], 1e-12f));
        }
    }
}

__global__ void scatter_csr(int Etot) {
    int e = blockIdx.x * blockDim.x + threadIdx.x;
    if (e >= Etot) return;
    int d = g_dst[e];
    int pos = atomicAdd(&g_woff[d], 1);
    if (pos >= 0 && pos < MAXET) g_csr[pos] = g_src[e];
}

// ---------------- GAT1: projected attention vectors ---------------------------
__global__ void proj_att1(const float* __restrict__ W1,
                          const float* __restrict__ a1s,
                          const float* __restrict__ a1d) {
    int t = threadIdx.x;
    if (t >= 80) return;
    int which = t / 40;
    int r = t % 40;
    int k = r / 4, h = r % 4;
    const float* a = which ? a1d : a1s;
    float s = 0.0f;
    for (int c = 0; c < 64; c++) s += W1[k * 256 + h * 64 + c] * a[h * 64 + c];
    if (which) g_wd1[k * 4 + h] = s; else g_ws1[k * 4 + h] = s;
}

__global__ void att1_scores(const float* __restrict__ x, int n) {
    int i = blockIdx.x * blockDim.x + threadIdx.x;
    if (i >= n) return;
    float xr[10];
    #pragma unroll
    for (int k = 0; k < 10; k++) xr[k] = x[(size_t)i * 10 + k];
    #pragma unroll
    for (int h = 0; h < 4; h++) {
        float s1 = 0.0f, s2 = 0.0f;
        #pragma unroll
        for (int k = 0; k < 10; k++) {
            s1 += xr[k] * g_ws1[k * 4 + h];
            s2 += xr[k] * g_wd1[k * 4 + h];
        }
        g_es[i * 4 + h] = s1;
        g_ed[i * 4 + h] = s2;
    }
}

// 4 threads per node: one per head
__global__ void gat1_agg(const float* __restrict__ x, int n) {
    int t = blockIdx.x * blockDim.x + threadIdx.x;
    int d = t >> 2, h = t & 3;
    if (d >= n) return;
    int r0 = g_rp[d];
    int deg = g_rp[d + 1] - r0;
    if (r0 < 0) r0 = 0;
    if (deg < 0) deg = 0;
    if (r0 + deg > MAXET) deg = MAXET - r0 > 0 ? MAXET - r0 : 0;

    float edv = g_ed[d * 4 + h];

    float m = -3.402823466e38f;
    for (int j = 0; j < deg; j++) {
        int s = g_csr[r0 + j];
        float v = g_es[s * 4 + h] + edv;
        v = v >= 0.0f ? v : 0.2f * v;
        m = fmaxf(m, v);
    }
    float ssum = 0.0f;
    float acc[10];
    #pragma unroll
    for (int k = 0; k < 10; k++) acc[k] = 0.0f;
    for (int j = 0; j < deg; j++) {
        int s = g_csr[r0 + j];
        float v = g_es[s * 4 + h] + edv;
        v = v >= 0.0f ? v : 0.2f * v;
        float ex = __expf(v - m);
        ssum += ex;
        const float* xr = x + (size_t)s * 10;
        #pragma unroll
        for (int k = 0; k < 10; k++) acc[k] += ex * xr[k];
    }
    float inv = 1.0f / (ssum + 1e-16f);
    #pragma unroll
    for (int k = 0; k < 10; k++)
        g_xagg[(size_t)d * 40 + h * 10 + k] = acc[k] * inv;
}

__global__ void gat1_out(const float* __restrict__ W1, const float* __restrict__ b1,
                         float* __restrict__ out, int n) {
    __shared__ float xs[8][40];
    int c = threadIdx.x;
    int row0 = blockIdx.x * 8;
    int h = c >> 6;
    float w[10];
    #pragma unroll
    for (int k = 0; k < 10; k++) w[k] = W1[k * 256 + c];
    for (int t = threadIdx.x; t < 8 * 40; t += 256) {
        int r = t / 40, k = t - r * 40;
        int gr = row0 + r;
        xs[r][k] = (gr < n) ? g_xagg[(size_t)gr * 40 + k] : 0.0f;
    }
    __syncthreads();
    float bc = b1[c];
    for (int r = 0; r < 8; r++) {
        int gr = row0 + r;
        if (gr >= n) break;
        float acc = 0.0f;
        #pragma unroll
        for (int k = 0; k < 10; k++) acc += xs[r][h * 10 + k] * w[k];
        float o = acc + bc;
        out[(size_t)gr * 256 + c] = o > 0.0f ? o : expm1f(o);
    }
}

// ---------------- tf32 tensor-core GEMM ---------------------------------------
__device__ __forceinline__ uint32_t f2tf32(float f) {
    uint32_t r;
    asm("cvt.rna.tf32.f32 %0, %1;" : "=r"(r) : "f"(f));
    return r;
}

__device__ __forceinline__ void mma_tf32(float* c, const uint32_t* a,
                                         uint32_t b0, uint32_t b1) {
    asm volatile(
        "mma.sync.aligned.m16n8k8.row.col.f32.tf32.tf32.f32 "
        "{%0,%1,%2,%3}, {%4,%5,%6,%7}, {%8,%9}, {%0,%1,%2,%3};"
        : "+f"(c[0]), "+f"(c[1]), "+f"(c[2]), "+f"(c[3])
        : "r"(a[0]), "r"(a[1]), "r"(a[2]), "r"(a[3]), "r"(b0), "r"(b1));
}

__global__ void sgemm_tf32(const float* __restrict__ A, const float* __restrict__ B,
                           float* __restrict__ C, int M, int N, int K)
{
    __shared__ float As[16][132];
    __shared__ float Bs[16][132];
    int tid = threadIdx.x;
    int lane = tid & 31, warp = tid >> 5;
    int warp_m = warp & 3, warp_n = warp >> 2;
    int grp = lane >> 2, tig = lane & 3;
    int rowBase = blockIdx.x * 128;
    int colBase = blockIdx.y * 128;

    float c[2][8][4];
    #pragma unroll
    for (int sm = 0; sm < 2; sm++)
        #pragma unroll
        for (int n8 = 0; n8 < 8; n8++)
            #pragma unroll
            for (int q = 0; q < 4; q++) c[sm][n8][q] = 0.0f;

    for (int k0 = 0; k0 < K; k0 += 16) {
        #pragma unroll
        for (int q = 0; q < 2; q++) {
            int idx = tid * 2 + q;
            int m = idx >> 2, kq = (idx & 3) * 4;
            int gr = rowBase + m;
            float4 v = make_float4(0.f, 0.f, 0.f, 0.f);
            if (gr < M) v = *(const float4*)(A + (size_t)gr * K + k0 + kq);
            As[kq + 0][m] = __uint_as_float(f2tf32(v.x));
            As[kq + 1][m] = __uint_as_float(f2tf32(v.y));
            As[kq + 2][m] = __uint_as_float(f2tf32(v.z));
            As[kq + 3][m] = __uint_as_float(f2tf32(v.w));
        }
        #pragma unroll
        for (int q = 0; q < 2; q++) {
            int idx = tid * 2 + q;
            int kk = idx >> 5, n4 = (idx & 31) * 4;
            int gc = colBase + n4;
            float4 v = make_float4(0.f, 0.f, 0.f, 0.f);
            if (gc + 3 < N) v = *(const float4*)(B + (size_t)(k0 + kk) * N + gc);
            Bs[kk][n4 + 0] = __uint_as_float(f2tf32(v.x));
            Bs[kk][n4 + 1] = __uint_as_float(f2tf32(v.y));
            Bs[kk][n4 + 2] = __uint_as_float(f2tf32(v.z));
            Bs[kk][n4 + 3] = __uint_as_float(f2tf32(v.w));
        }
        __syncthreads();
        #pragma unroll
        for (int kc = 0; kc < 16; kc += 8) {
            uint32_t afr[2][4];
            #pragma unroll
            for (int sm = 0; sm < 2; sm++) {
                int r = warp_m * 32 + sm * 16;
                afr[sm][0] = __float_as_uint(As[kc + tig    ][r + grp    ]);
                afr[sm][1] = __float_as_uint(As[kc + tig    ][r + grp + 8]);
                afr[sm][2] = __float_as_uint(As[kc + tig + 4][r + grp    ]);
                afr[sm][3] = __float_as_uint(As[kc + tig + 4][r + grp + 8]);
            }
            #pragma unroll
            for (int n8 = 0; n8 < 8; n8++) {
                int cb = warp_n * 64 + n8 * 8;
                uint32_t b0 = __float_as_uint(Bs[kc + tig    ][cb + grp]);
                uint32_t b1 = __float_as_uint(Bs[kc + tig + 4][cb + grp]);
                mma_tf32(c[0][n8], afr[0], b0, b1);
                mma_tf32(c[1][n8], afr[1], b0, b1);
            }
        }
        __syncthreads();
    }

    #pragma unroll
    for (int sm = 0; sm < 2; sm++) {
        int r0 = rowBase + warp_m * 32 + sm * 16 + grp;
        #pragma unroll
        for (int n8 = 0; n8 < 8; n8++) {
            int c0 = colBase + warp_n * 64 + n8 * 8 + tig * 2;
            if (r0 < M && c0 + 1 < N) {
                C[(size_t)r0 * N + c0    ] = c[sm][n8][0];
                C[(size_t)r0 * N + c0 + 1] = c[sm][n8][1];
            }
            if (r0 + 8 < M && c0 + 1 < N) {
                C[(size_t)(r0 + 8) * N + c0    ] = c[sm][n8][2];
                C[(size_t)(r0 + 8) * N + c0 + 1] = c[sm][n8][3];
            }
        }
    }
}

// ---------------- generic 64-tile SGEMM (GCN2 only) ---------------------------
__global__ void sgemm(const float* __restrict__ A, const float* __restrict__ B,
                      float* __restrict__ C, int M, int N, int K)
{
    __shared__ float As[16][64];
    __shared__ float Bs[16][64];
    int tid = threadIdx.y * 16 + threadIdx.x;
    int rowBase = blockIdx.x * 64;
    int colBase = blockIdx.y * 64;
    float acc[4][4] = {};
    for (int k0 = 0; k0 < K; k0 += 16) {
        #pragma unroll
        for (int i = 0; i < 4; i++) {
            int idx = tid * 4 + i;
            int m  = idx >> 4;
            int kk = idx & 15;
            int gr = rowBase + m, gc = k0 + kk;
            As[kk][m] = (gr < M && gc < K) ? A[(size_t)gr * K + gc] : 0.0f;
        }
        #pragma unroll
        for (int i = 0; i < 4; i++) {
            int idx = tid * 4 + i;
            int kk = idx >> 6;
            int nn = idx & 63;
            int gr = k0 + kk, gc = colBase + nn;
            Bs[kk][nn] = (gr < K && gc < N) ? B[(size_t)gr * N + gc] : 0.0f;
        }
        __syncthreads();
        #pragma unroll
        for (int kk = 0; kk < 16; kk++) {
            float a[4], b[4];
            #pragma unroll
            for (int i = 0; i < 4; i++) a[i] = As[kk][threadIdx.y * 4 + i];
            #pragma unroll
            for (int j = 0; j < 4; j++) b[j] = Bs[kk][threadIdx.x * 4 + j];
            #pragma unroll
            for (int i = 0; i < 4; i++)
                #pragma unroll
                for (int j = 0; j < 4; j++) acc[i][j] += a[i] * b[j];
        }
        __syncthreads();
    }
    #pragma unroll
    for (int i = 0; i < 4; i++) {
        int gr = rowBase + threadIdx.y * 4 + i;
        if (gr >= M) continue;
        #pragma unroll
        for (int j = 0; j < 4; j++) {
            int gc = colBase + threadIdx.x * 4 + j;
            if (gc < N) C[(size_t)gr * N + gc] = acc[i][j];
        }
    }
}

// ---------------- attention scores (GAT2): warp per node ----------------------
template<int H, int C>
__global__ void att_scores_w(const float* __restrict__ h,
                             const float* __restrict__ a_src,
                             const float* __restrict__ a_dst,
                             float* __restrict__ es, float* __restrict__ ed, int n)
{
    const int HC = H * C;
    int gtid = blockIdx.x * blockDim.x + threadIdx.x;
    int node = gtid >> 5;
    int lane = threadIdx.x & 31;
    if (node >= n) return;
    const float4* row = (const float4*)(h + (size_t)node * HC);
    const float4* as4 = (const float4*)a_src;
    const float4* ad4 = (const float4*)a_dst;
    float accs[H], accd[H];
    #pragma unroll
    for (int hh = 0; hh < H; hh++) { accs[hh] = 0.0f; accd[hh] = 0.0f; }
    #pragma unroll
    for (int it = 0; it < HC / 128; it++) {
        int i4 = it * 32 + lane;
        float4 v = row[i4];
        int hh = i4 >> 4;
        float4 a = as4[hh * 16 + (i4 & 15)];
        float4 b = ad4[hh * 16 + (i4 & 15)];
        accs[hh] += v.x*a.x + v.y*a.y + v.z*a.z + v.w*a.w;
        accd[hh] += v.x*b.x + v.y*b.y + v.z*b.z + v.w*b.w;
    }
    #pragma unroll
    for (int hh = 0; hh < H; hh++) {
        #pragma unroll
        for (int off = 16; off; off >>= 1) {
            accs[hh] += __shfl_xor_sync(0xffffffffu, accs[hh], off);
            accd[hh] += __shfl_xor_sync(0xffffffffu, accd[hh], off);
        }
    }
    if (lane == 0) {
        #pragma unroll
        for (int hh = 0; hh < H; hh++) {
            es[node * H + hh] = accs[hh];
            ed[node * H + hh] = accd[hh];
        }
    }
}

// ---------------- GAT2 aggregation: warp per node (H=2, C=64) -----------------
// 3 shuffle passes: max, exp-sum, aggregate. No smem, no block barriers.
__global__ void gat2_agg_warp(const float* __restrict__ h,
                              const float* __restrict__ es, const float* __restrict__ ed,
                              const float* __restrict__ b,
                              float* __restrict__ out, int n)
{
    int gtid = blockIdx.x * blockDim.x + threadIdx.x;
    int node = gtid >> 5;
    int lane = threadIdx.x & 31;
    if (node >= n) return;

    int r0 = g_rp[node];
    int deg = g_rp[node + 1] - r0;
    if (r0 < 0) r0 = 0;
    if (deg < 0) deg = 0;
    if (r0 + deg > MAXET) deg = MAXET - r0 > 0 ? MAXET - r0 : 0;

    float edv0 = ed[node * 2 + 0];
    float edv1 = ed[node * 2 + 1];

    // pass 1: per-head max (lanes stride edges)
    float m0 = -3.402823466e38f, m1 = -3.402823466e38f;
    for (int j = lane; j < deg; j += 32) {
        int s = g_csr[r0 + j];
        float v0 = es[s * 2 + 0] + edv0;
        float v1 = es[s * 2 + 1] + edv1;
        v0 = v0 >= 0.0f ? v0 : 0.2f * v0;
        v1 = v1 >= 0.0f ? v1 : 0.2f * v1;
        m0 = fmaxf(m0, v0);
        m1 = fmaxf(m1, v1);
    }
    #pragma unroll
    for (int off = 16; off; off >>= 1) {
        m0 = fmaxf(m0, __shfl_xor_sync(0xffffffffu, m0, off));
        m1 = fmaxf(m1, __shfl_xor_sync(0xffffffffu, m1, off));
    }

    // pass 2: per-head exp-sum
    float s0 = 0.0f, s1 = 0.0f;
    for (int j = lane; j < deg; j += 32) {
        int s = g_csr[r0 + j];
        float v0 = es[s * 2 + 0] + edv0;
        float v1 = es[s * 2 + 1] + edv1;
        v0 = v0 >= 0.0f ? v0 : 0.2f * v0;
        v1 = v1 >= 0.0f ? v1 : 0.2f * v1;
        s0 += __expf(v0 - m0);
        s1 += __expf(v1 - m1);
    }
    #pragma unroll
    for (int off = 16; off; off >>= 1) {
        s0 += __shfl_xor_sync(0xffffffffu, s0, off);
        s1 += __shfl_xor_sync(0xffffffffu, s1, off);
    }
    float inv0 = 1.0f / (s0 + 1e-16f);
    float inv1 = 1.0f / (s1 + 1e-16f);

    // pass 3: aggregate (serial over edges; lane covers channels lane+32q)
    float acc[4] = {0.f, 0.f, 0.f, 0.f};
    for (int j = 0; j < deg; j++) {
        int s = g_csr[r0 + j];                 // broadcast
        float v0 = es[s * 2 + 0] + edv0;       // broadcast loads
        float v1 = es[s * 2 + 1] + edv1;
        v0 = v0 >= 0.0f ? v0 : 0.2f * v0;
        v1 = v1 >= 0.0f ? v1 : 0.2f * v1;
        float ex0 = __expf(v0 - m0);
        float ex1 = __expf(v1 - m1);
        const float* hr = h + (size_t)s * 128;
        acc[0] += ex0 * hr[lane     ];
        acc[1] += ex0 * hr[lane + 32];
        acc[2] += ex1 * hr[lane + 64];
        acc[3] += ex1 * hr[lane + 96];
    }

    float* orow = out + (size_t)node * 128;
    #pragma unroll
    for (int q = 0; q < 4; q++) {
        int c = lane + 32 * q;
        float inv = (q < 2) ? inv0 : inv1;
        float o = acc[q] * inv + b[c];
        orow[c] = o > 0.0f ? o : expm1f(o);
    }
}

// ---------------- fused GCN aggregation ---------------------------------------
template<int F>
__global__ void gcn_fused(const float* __restrict__ h,
                          const float* __restrict__ dinv,
                          const float* __restrict__ b,
                          float* __restrict__ out, int n)
{
    const int G = 128 / F;
    int g = threadIdx.x / F, c = threadIdx.x % F;
    int d = blockIdx.x * G + g;
    if (d >= n) return;
    int r0 = g_rp[d], deg = g_rp[d + 1] - r0;
    if (r0 < 0) r0 = 0;
    if (deg < 0) deg = 0;
    if (r0 + deg > MAXET) deg = MAXET - r0 > 0 ? MAXET - r0 : 0;
    float acc = 0.0f;
    int j = 0;
    for (; j + 4 <= deg; j += 4) {
        int s0 = g_csr[r0 + j + 0];
        int s1 = g_csr[r0 + j + 1];
        int s2 = g_csr[r0 + j + 2];
        int s3 = g_csr[r0 + j + 3];
        acc += dinv[s0] * h[(size_t)s0 * F + c]
             + dinv[s1] * h[(size_t)s1 * F + c]
             + dinv[s2] * h[(size_t)s2 * F + c]
             + dinv[s3] * h[(size_t)s3 * F + c];
    }
    for (; j < deg; j++) {
        int s = g_csr[r0 + j];
        acc += dinv[s] * h[(size_t)s * F + c];
    }
    float o = dinv[d] * acc + b[c];
    out[(size_t)d * F + c] = o > 0.0f ? o : expm1f(o);
}

// ---------------- heads -------------------------------------------------------
__global__ void zone_head(const float* __restrict__ h, const float* __restrict__ Wz,
                          const float* __restrict__ bz, float* out, int n)
{
    int idx = blockIdx.x * blockDim.x + threadIdx.x;
    if (idx >= n * 4) return;
    int i = idx >> 2, j = idx & 3;
    float acc = bz[j];
    const float* row = h + (size_t)i * 32;
    #pragma unroll
    for (int k = 0; k < 32; k++) acc += row[k] * Wz[k * 4 + j];
    out[idx] = acc;
}

__global__ void zero_gsum() {
    if (threadIdx.x < 32) g_gsum[threadIdx.x] = 0.0f;
}

__global__ void mean_reduce(const float* __restrict__ h, int n)
{
    __shared__ float sm[256];
    int ch = threadIdx.x & 31;
    int grp = threadIdx.x >> 5;
    float acc = 0.0f;
    for (int r = blockIdx.x * 8 + grp; r < n; r += gridDim.x * 8)
        acc += h[(size_t)r * 32 + ch];
    sm[threadIdx.x] = acc;
    __syncthreads();
    if (grp == 0) {
        float t = 0.0f;
        #pragma unroll
        for (int g = 0; g < 8; g++) t += sm[g * 32 + ch];
        atomicAdd(&g_gsum[ch], t);
    }
}

__global__ void heads_kernel(const float* Ws, const float* bs,
                             const float* Wa, const float* ba,
                             const float* Wc, const float* bc,
                             float* out3, int n)
{
    int t = threadIdx.x;
    float mean = g_gsum[t] / (float)n;
    float vs = mean * Ws[t];
    float va = mean * Wa[t];
    float vc = mean * Wc[t];
    #pragma unroll
    for (int o = 16; o > 0; o >>= 1) {
        vs += __shfl_down_sync(0xffffffffu, vs, o);
        va += __shfl_down_sync(0xffffffffu, va, o);
        vc += __shfl_down_sync(0xffffffffu, vc, o);
    }
    if (t == 0) {
        out3[0] = 1.0f / (1.0f + expf(-(vs + bs[0])));
        out3[1] = 1.0f / (1.0f + expf(-(va + ba[0])));
        out3[2] = 1.0f / (1.0f + expf(-(vc + bc[0])));
    }
}

// ---------------- launch ------------------------------------------------------
extern "C" void kernel_launch(void* const* d_in, const int* in_sizes, int n_in,
                              void* d_out, int out_size)
{
    const float* x      = (const float*)d_in[0];
    const void*  ei     = d_in[1];
    const float* W1     = (const float*)d_in[2];
    const float* a1_src = (const float*)d_in[3];
    const float* a1_dst = (const float*)d_in[4];
    const float* b1     = (const float*)d_in[5];
    const float* W2     = (const float*)d_in[6];
    const float* a2_src = (const float*)d_in[7];
    const float* a2_dst = (const float*)d_in[8];
    const float* b2     = (const float*)d_in[9];
    const float* W3     = (const float*)d_in[10];
    const float* b3     = (const float*)d_in[11];
    const float* W4     = (const float*)d_in[12];
    const float* b4     = (const float*)d_in[13];
    const float* Wz     = (const float*)d_in[14];
    const float* bz     = (const float*)d_in[15];
    const float* Ws     = (const float*)d_in[16];
    const float* bs     = (const float*)d_in[17];
    const float* Wa     = (const float*)d_in[18];
    const float* ba     = (const float*)d_in[19];
    const float* Wc     = (const float*)d_in[20];
    const float* bc     = (const float*)d_in[21];

    int n = in_sizes[0] / 10;
    int E = in_sizes[1] / 2;
    int Etot = E + n;
    int nb = CDIV(n, SCAN_CHUNK);

    float* out      = (float*)d_out;
    float* out_zone = out;
    float* out_sc   = out + (size_t)n * 4;
    float* out_h    = out + (size_t)n * 4 + 3;

    float *p_o1, *p_h2, *p_o2, *p_g3, *p_o3, *p_g4, *p_es, *p_ed, *p_dinv;
    cudaGetSymbolAddress((void**)&p_o1,  g_o1);
    cudaGetSymbolAddress((void**)&p_h2,  g_h2);
    cudaGetSymbolAddress((void**)&p_o2,  g_o2);
    cudaGetSymbolAddress((void**)&p_g3,  g_g3);
    cudaGetSymbolAddress((void**)&p_o3,  g_o3);
    cudaGetSymbolAddress((void**)&p_g4,  g_g4);
    cudaGetSymbolAddress((void**)&p_es,  g_es);
    cudaGetSymbolAddress((void**)&p_ed,  g_ed);
    cudaGetSymbolAddress((void**)&p_dinv,g_dinv);

    const int T = 256;
    dim3 tb(16, 16);

    // ---- CSR build ----
    sniff_kernel<<<1, 128>>>(ei);
    zero_degi<<<CDIV(n, T), T>>>(n);
    decode_count<<<CDIV(Etot, T), T>>>(ei, E, n);
    scan_a<<<nb, 256>>>(n);
    scan_b<<<1, 32>>>(nb, n);
    scan_c<<<nb, 256>>>(n);
    scatter_csr<<<CDIV(Etot, T), T>>>(Etot);

    // ---- GAT1 ----
    proj_att1<<<1, 128>>>(W1, a1_src, a1_dst);
    att1_scores<<<CDIV(n, T), T>>>(x, n);
    gat1_agg<<<CDIV(n * 4, 128), 128>>>(x, n);
    gat1_out<<<CDIV(n, 8), 256>>>(W1, b1, p_o1, n);

    // ---- GAT2: 256 -> H=2, C=64 ----
    sgemm_tf32<<<dim3(CDIV(n, 128), 1), 256>>>(p_o1, W2, p_h2, n, 128, 256);
    att_scores_w<2, 64><<<CDIV(n * 32, T), T>>>(p_h2, a2_src, a2_dst, p_es, p_ed, n);
    gat2_agg_warp<<<CDIV(n * 32, T), T>>>(p_h2, p_es, p_ed, b2, p_o2, n);

    // ---- GCN1: 128 -> 64 ----
    sgemm_tf32<<<dim3(CDIV(n, 128), 1), 256>>>(p_o2, W3, p_g3, n, 64, 128);
    gcn_fused<64><<<CDIV(n, 2), 128>>>(p_g3, p_dinv, b3, p_o3, n);

    // ---- GCN2: 64 -> 32 ----
    sgemm<<<dim3(CDIV(n, 64), 1), tb>>>(p_o3, W4, p_g4, n, 32, 64);
    gcn_fused<32><<<CDIV(n, 4), 128>>>(p_g4, p_dinv, b4, out_h, n);

    // ---- heads ----
    zone_head<<<CDIV(n * 4, T), T>>>(out_h, Wz, bz, out_zone, n);
    zero_gsum<<<1, 32>>>();
    mean_reduce<<<128, 256>>>(out_h, n);
    heads_kernel<<<1, 32>>>(Ws, bs, Wa, ba, Wc, bc, out_sc, n);
}